// round 11
// baseline (speedup 1.0000x reference)
#include <cuda_runtime.h>
#include <cuda_fp16.h>
#include <cstdint>

#define NG 2500
#define NT 20000
#define NE 640000
#define SRCD 128
#define DSTD 500
#define HID 128
#define OUTD 128
#define NCLS 16
#define KP1 512               // padded K for layer-1 self GEMM

// ---------------- scratch (device globals; no allocation allowed) ----------------
__device__ int    g_cnt[NT];
__device__ int    g_rowstart[NT];
__device__ int    g_pos[NE];
__device__ int    g_sorted[NE];
__device__ __half g_train16[(size_t)NT * KP1];
__device__ __half g_gene16[NG * SRCD];
__device__ __half g_agg16[(size_t)NT * HID];
__device__ __half g_h1[(size_t)NT * HID];
__device__ __half g_h2[(size_t)NT * OUTD];
// transposed weights, [N=128, Kpad] K-major, fp16, zero-padded
__device__ __half g_Bt1s[128 * KP1];
__device__ __half g_Bt1n[128 * 128];
__device__ __half g_Bt2s[128 * 128];
__device__ __half g_Bt2n[128 * 128];
__device__ __half g_Btc1[128 * 128];

__device__ __forceinline__ uint32_t smem_to_u32(const void* p) {
    uint32_t a;
    asm("{ .reg .u64 t; cvta.to.shared.u64 t, %1; cvt.u32.u64 %0, t; }" : "=r"(a) : "l"(p));
    return a;
}
__device__ __forceinline__ uint32_t h2u(__half2 h) { return *reinterpret_cast<uint32_t*>(&h); }

// ---------------- 1a) main-stream prep: gene fp16 cache + zero counters ----------------
__global__ void prep_main_kernel(const float* __restrict__ gene) {
    int stride = gridDim.x * blockDim.x;
    int t0 = blockIdx.x * blockDim.x + threadIdx.x;
    if (blockIdx.y == 0) {
        int N = NG * SRCD / 4;
        for (int i = t0; i < N; i += stride) {
            float4 v = reinterpret_cast<const float4*>(gene)[i];
            uint2 u;
            u.x = h2u(__floats2half2_rn(v.x, v.y));
            u.y = h2u(__floats2half2_rn(v.z, v.w));
            reinterpret_cast<uint2*>(g_gene16)[i] = u;
        }
    } else {
        for (int i = t0; i < NT; i += stride) g_cnt[i] = 0;
    }
}

// ---------------- 1b) side-stream prep: weight transposes + train fp16 pad ----------------
__global__ void prep_side_kernel(const float* __restrict__ train,
                                 const float* __restrict__ W1s, const float* __restrict__ W1n,
                                 const float* __restrict__ W2s, const float* __restrict__ W2n,
                                 const float* __restrict__ Wc1) {
    int task = blockIdx.y;
    int stride = gridDim.x * blockDim.x;
    int t0 = blockIdx.x * blockDim.x + threadIdx.x;
    if (task < 5) {
        const float* src; __half* dst; int K, Kpad;
        if      (task == 0) { src = W1s; dst = g_Bt1s; K = DSTD; Kpad = KP1; }
        else if (task == 1) { src = W1n; dst = g_Bt1n; K = HID;  Kpad = 128; }
        else if (task == 2) { src = W2s; dst = g_Bt2s; K = HID;  Kpad = 128; }
        else if (task == 3) { src = W2n; dst = g_Bt2n; K = HID;  Kpad = 128; }
        else                { src = Wc1; dst = g_Btc1; K = OUTD; Kpad = 128; }
        int N = 128 * Kpad;
        for (int i = t0; i < N; i += stride) {
            int n = i / Kpad, k = i % Kpad;
            dst[i] = (k < K) ? __float2half_rn(src[k * 128 + n]) : __half(0.f);
        }
    } else {
        // train [NT,500] fp32 -> [NT,512] fp16 zero-padded, 8 elems/thread
        int N = NT * (KP1 / 8);
        for (int i = t0; i < N; i += stride) {
            int r = i >> 6;
            int k0 = (i & 63) << 3;
            float f[8];
            #pragma unroll
            for (int j = 0; j < 8; j++) {
                int k = k0 + j;
                f[j] = (k < DSTD) ? train[(size_t)r * DSTD + k] : 0.f;
            }
            uint4 u;
            u.x = h2u(__floats2half2_rn(f[0], f[1]));
            u.y = h2u(__floats2half2_rn(f[2], f[3]));
            u.z = h2u(__floats2half2_rn(f[4], f[5]));
            u.w = h2u(__floats2half2_rn(f[6], f[7]));
            *reinterpret_cast<uint4*>(&g_train16[(size_t)r * KP1 + k0]) = u;
        }
    }
}

// ---------------- 2) histogram + within-row rank (ILP 4) ----------------
__global__ void hist_kernel(const int* __restrict__ edst) {
    int base = blockIdx.x * 1024 + threadIdx.x;
    int d0 = edst[base];
    int d1 = edst[base + 256];
    int d2 = edst[base + 512];
    int d3 = edst[base + 768];
    g_pos[base      ] = atomicAdd(&g_cnt[d0], 1);
    g_pos[base + 256] = atomicAdd(&g_cnt[d1], 1);
    g_pos[base + 512] = atomicAdd(&g_cnt[d2], 1);
    g_pos[base + 768] = atomicAdd(&g_cnt[d3], 1);
}

// ---------------- 3) exclusive scan, shuffle-based, 1 block ----------------
__global__ __launch_bounds__(1024) void scan_kernel() {
    __shared__ int wsum[32];
    int t = threadIdx.x, lane = t & 31, w = t >> 5;
    const int L = 20;
    int local[L];
    int s = 0;
    if (t < 1000) {
        int base = t * L;
        #pragma unroll
        for (int j = 0; j < L; j++) { local[j] = s; s += g_cnt[base + j]; }
    }
    int incl = s;
    #pragma unroll
    for (int d = 1; d < 32; d <<= 1) {
        int x = __shfl_up_sync(0xFFFFFFFFu, incl, d);
        if (lane >= d) incl += x;
    }
    if (lane == 31) wsum[w] = incl;
    __syncthreads();
    if (w == 0) {
        int v = wsum[lane];
        #pragma unroll
        for (int d = 1; d < 32; d <<= 1) {
            int x = __shfl_up_sync(0xFFFFFFFFu, v, d);
            if (lane >= d) v += x;
        }
        wsum[lane] = v;
    }
    __syncthreads();
    int off = (w > 0 ? wsum[w - 1] : 0) + incl - s;
    if (t < 1000) {
        int base = t * L;
        #pragma unroll
        for (int j = 0; j < L; j++) g_rowstart[base + j] = off + local[j];
    }
}

// ---------------- 4) pure scatter (no atomics, ILP 4) ----------------
__global__ void scatter_kernel(const int* __restrict__ esrc, const int* __restrict__ edst) {
    int base = blockIdx.x * 1024 + threadIdx.x;
    int d0 = edst[base],       d1 = edst[base + 256];
    int d2 = edst[base + 512], d3 = edst[base + 768];
    int p0 = g_pos[base],       p1 = g_pos[base + 256];
    int p2 = g_pos[base + 512], p3 = g_pos[base + 768];
    int s0 = esrc[base],       s1 = esrc[base + 256];
    int s2 = esrc[base + 512], s3 = esrc[base + 768];
    g_sorted[g_rowstart[d0] + p0] = s0;
    g_sorted[g_rowstart[d1] + p1] = s1;
    g_sorted[g_rowstart[d2] + p2] = s2;
    g_sorted[g_rowstart[d3] + p3] = s3;
}

// ---------------- 5) mean aggregation from fp16 gene cache -> fp16 agg ----------------
__global__ void agg_kernel() {
    int d = blockIdx.x * 8 + (threadIdx.x >> 5);
    if (d >= NT) return;
    int lane = threadIdx.x & 31;
    int start = g_rowstart[d];
    int n = g_cnt[d];
    const uint2* G = reinterpret_cast<const uint2*>(g_gene16);

    float4 a0 = {0.f, 0.f, 0.f, 0.f}, a1 = a0, a2 = a0, a3 = a0;
    int e = 0;
    for (; e + 4 <= n; e += 4) {
        int s0 = g_sorted[start + e + 0];
        int s1 = g_sorted[start + e + 1];
        int s2 = g_sorted[start + e + 2];
        int s3 = g_sorted[start + e + 3];
        uint2 u0 = G[s0 * 32 + lane];
        uint2 u1 = G[s1 * 32 + lane];
        uint2 u2 = G[s2 * 32 + lane];
        uint2 u3 = G[s3 * 32 + lane];
        float2 f;
        f = __half22float2(*reinterpret_cast<__half2*>(&u0.x)); a0.x += f.x; a0.y += f.y;
        f = __half22float2(*reinterpret_cast<__half2*>(&u0.y)); a0.z += f.x; a0.w += f.y;
        f = __half22float2(*reinterpret_cast<__half2*>(&u1.x)); a1.x += f.x; a1.y += f.y;
        f = __half22float2(*reinterpret_cast<__half2*>(&u1.y)); a1.z += f.x; a1.w += f.y;
        f = __half22float2(*reinterpret_cast<__half2*>(&u2.x)); a2.x += f.x; a2.y += f.y;
        f = __half22float2(*reinterpret_cast<__half2*>(&u2.y)); a2.z += f.x; a2.w += f.y;
        f = __half22float2(*reinterpret_cast<__half2*>(&u3.x)); a3.x += f.x; a3.y += f.y;
        f = __half22float2(*reinterpret_cast<__half2*>(&u3.y)); a3.z += f.x; a3.w += f.y;
    }
    for (; e < n; e++) {
        int s = g_sorted[start + e];
        uint2 u = G[s * 32 + lane];
        float2 f;
        f = __half22float2(*reinterpret_cast<__half2*>(&u.x)); a0.x += f.x; a0.y += f.y;
        f = __half22float2(*reinterpret_cast<__half2*>(&u.y)); a0.z += f.x; a0.w += f.y;
    }
    float4 acc;
    acc.x = a0.x + a1.x + a2.x + a3.x;
    acc.y = a0.y + a1.y + a2.y + a3.y;
    acc.z = a0.z + a1.z + a2.z + a3.z;
    acc.w = a0.w + a1.w + a2.w + a3.w;
    float inv = 1.0f / fmaxf((float)n, 1.0f);
    uint2 u;
    u.x = h2u(__floats2half2_rn(acc.x * inv, acc.y * inv));
    u.y = h2u(__floats2half2_rn(acc.z * inv, acc.w * inv));
    reinterpret_cast<uint2*>(g_agg16)[(size_t)d * 32 + lane] = u;
}

// ---------------- 6) fp16 mma.sync dual GEMM (m16n8k16) + ldmatrix, cp.async 2-buf -------
#define KC    64                 // k-chunk (halves)
#define KPADH 72                 // smem row stride in halves (rows walk banks by 4 — conflict-free)
#define ABUFH (128 * KPADH)      // halves per buffer
#define SM_BIASF (2 * ABUFH)
#define SM_W2F   (SM_BIASF + 128)
#define SM_B2F   (SM_W2F + 2048)
#define SM_TOTAL ((SM_B2F + 16) * 4)
#define TSTRIDE  130

__global__ __launch_bounds__(256, 2)
void mma_gemm_dual(const __half* __restrict__ A1, int lda1, int K1, const __half* __restrict__ Bt1,
                   const __half* __restrict__ A2, int lda2, int K2, const __half* __restrict__ Bt2,
                   const float* __restrict__ bias, __half* __restrict__ C, int M,
                   const float* __restrict__ Wc2, const float* __restrict__ bc2,
                   float* __restrict__ outp, int fuse_cls) {
    extern __shared__ float smemf[];
    __half* As = reinterpret_cast<__half*>(smemf);
    __half* Bs = As + 2 * ABUFH;
    float* sbias = smemf + SM_BIASF;

    int tid = threadIdx.x;
    int wid = tid >> 5, lane = tid & 31;
    int wm = wid & 3, wn = wid >> 2;
    int g  = lane >> 2, tq = lane & 3;
    int row0 = blockIdx.x * 128;

    if (tid < 128) sbias[tid] = bias[tid];

    int nch1 = K1 / KC;
    int nch2 = K2 / KC;
    int nct  = nch1 + nch2;

    auto stage = [&](int c, int buf) {
        const __half* Ap; const __half* Bp; int lda, kb, k0;
        if (c < nch1) { Ap = A1; Bp = Bt1; lda = lda1; kb = K1; k0 = c * KC; }
        else          { Ap = A2; Bp = Bt2; lda = lda2; kb = K2; k0 = (c - nch1) * KC; }
        __half* Ad = As + buf * ABUFH;
        __half* Bd = Bs + buf * ABUFH;
        #pragma unroll
        for (int i = 0; i < 4; i++) {
            int idx = tid + i * 256;
            int r = idx >> 3, seg = idx & 7;
            int gr = row0 + r;
            int ok = gr < M;
            const __half* src = Ap + ((size_t)(ok ? gr : 0) * lda + k0 + seg * 8);
            uint32_t da = smem_to_u32(Ad + r * KPADH + seg * 8);
            asm volatile("cp.async.cg.shared.global [%0], [%1], 16, %2;"
                         :: "r"(da), "l"(src), "r"(ok ? 16 : 0));
            const __half* bsrc = Bp + ((size_t)r * kb + k0 + seg * 8);
            uint32_t db = smem_to_u32(Bd + r * KPADH + seg * 8);
            asm volatile("cp.async.cg.shared.global [%0], [%1], 16, %2;"
                         :: "r"(db), "l"(bsrc), "r"(16));
        }
        asm volatile("cp.async.commit_group;" ::: "memory");
    };

    float acc[2][8][4];
    #pragma unroll
    for (int mt = 0; mt < 2; mt++)
        #pragma unroll
        for (int nt = 0; nt < 8; nt++)
            #pragma unroll
            for (int q = 0; q < 4; q++) acc[mt][nt][q] = 0.f;

    // per-lane ldmatrix row/col offsets (in halves), constant across chunks
    int a_row = lane & 15;                        // matrix pair row
    int a_koff = (lane >> 4) << 3;                // 0 or 8
    int b_row = (lane & 7) + ((lane >> 4) << 3);  // row within 16-row group
    int b_koff = ((lane >> 3) & 1) << 3;          // 0 or 8

    stage(0, 0);

    #pragma unroll 1
    for (int c = 0; c < nct; c++) {
        int buf = c & 1;
        if (c + 1 < nct) {
            stage(c + 1, buf ^ 1);
            asm volatile("cp.async.wait_group 1;" ::: "memory");
        } else {
            asm volatile("cp.async.wait_group 0;" ::: "memory");
        }
        __syncthreads();

        uint32_t aAddr[2], bAddr[4];
        {
            uint32_t abase = smem_to_u32(As + buf * ABUFH);
            uint32_t bbase = smem_to_u32(Bs + buf * ABUFH);
            #pragma unroll
            for (int mt = 0; mt < 2; mt++)
                aAddr[mt] = abase + ((wm * 32 + mt * 16 + a_row) * KPADH + a_koff) * 2;
            #pragma unroll
            for (int q = 0; q < 4; q++)
                bAddr[q] = bbase + ((wn * 64 + q * 16 + b_row) * KPADH + b_koff) * 2;
        }

        #pragma unroll
        for (int ks = 0; ks < KC / 16; ks++) {
            int kb2 = ks * 32;                    // kk*2 bytes
            uint32_t afr[2][4];
            #pragma unroll
            for (int mt = 0; mt < 2; mt++) {
                asm volatile("ldmatrix.sync.aligned.m8n8.x4.shared.b16 {%0,%1,%2,%3}, [%4];"
                             : "=r"(afr[mt][0]), "=r"(afr[mt][1]),
                               "=r"(afr[mt][2]), "=r"(afr[mt][3])
                             : "r"(aAddr[mt] + kb2));
            }
            uint32_t bfr[8][2];
            #pragma unroll
            for (int q = 0; q < 4; q++) {
                asm volatile("ldmatrix.sync.aligned.m8n8.x4.shared.b16 {%0,%1,%2,%3}, [%4];"
                             : "=r"(bfr[2 * q][0]), "=r"(bfr[2 * q][1]),
                               "=r"(bfr[2 * q + 1][0]), "=r"(bfr[2 * q + 1][1])
                             : "r"(bAddr[q] + kb2));
            }
            #pragma unroll
            for (int mt = 0; mt < 2; mt++)
                #pragma unroll
                for (int nt = 0; nt < 8; nt++) {
                    asm volatile(
                        "mma.sync.aligned.m16n8k16.row.col.f32.f16.f16.f32 "
                        "{%0,%1,%2,%3}, {%4,%5,%6,%7}, {%8,%9}, {%0,%1,%2,%3};"
                        : "+f"(acc[mt][nt][0]), "+f"(acc[mt][nt][1]),
                          "+f"(acc[mt][nt][2]), "+f"(acc[mt][nt][3])
                        : "r"(afr[mt][0]), "r"(afr[mt][1]), "r"(afr[mt][2]), "r"(afr[mt][3]),
                          "r"(bfr[nt][0]), "r"(bfr[nt][1]));
                }
        }
        __syncthreads();
    }

    if (!fuse_cls) {
        #pragma unroll
        for (int mt = 0; mt < 2; mt++) {
            int r1 = row0 + wm * 32 + mt * 16 + g;
            int r2 = r1 + 8;
            #pragma unroll
            for (int nt = 0; nt < 8; nt++) {
                int col = wn * 64 + nt * 8 + tq * 2;
                float b0 = sbias[col], b1 = sbias[col + 1];
                float v10 = fmaxf(acc[mt][nt][0] + b0, 0.f);
                float v11 = fmaxf(acc[mt][nt][1] + b1, 0.f);
                float v20 = fmaxf(acc[mt][nt][2] + b0, 0.f);
                float v21 = fmaxf(acc[mt][nt][3] + b1, 0.f);
                if (r1 < M)
                    *reinterpret_cast<uint32_t*>(C + (size_t)r1 * 128 + col) =
                        h2u(__floats2half2_rn(v10, v11));
                if (r2 < M)
                    *reinterpret_cast<uint32_t*>(C + (size_t)r2 * 128 + col) =
                        h2u(__floats2half2_rn(v20, v21));
            }
        }
    } else {
        float* tS  = smemf;
        float* sW2 = smemf + SM_W2F;
        float* sb2 = smemf + SM_B2F;
        for (int i = tid; i < 128 * NCLS; i += 256) sW2[i] = Wc2[i];
        if (tid < NCLS) sb2[tid] = bc2[tid];
        #pragma unroll
        for (int mt = 0; mt < 2; mt++) {
            int lr1 = wm * 32 + mt * 16 + g;
            int lr2 = lr1 + 8;
            #pragma unroll
            for (int nt = 0; nt < 8; nt++) {
                int col = wn * 64 + nt * 8 + tq * 2;
                float b0 = sbias[col], b1 = sbias[col + 1];
                tS[lr1 * TSTRIDE + col]     = fmaxf(acc[mt][nt][0] + b0, 0.f);
                tS[lr1 * TSTRIDE + col + 1] = fmaxf(acc[mt][nt][1] + b1, 0.f);
                tS[lr2 * TSTRIDE + col]     = fmaxf(acc[mt][nt][2] + b0, 0.f);
                tS[lr2 * TSTRIDE + col + 1] = fmaxf(acc[mt][nt][3] + b1, 0.f);
            }
        }
        __syncthreads();
        int lrow = tid >> 1;
        int cg = (tid & 1) * 8;
        int grow = row0 + lrow;
        if (grow < M) {
            float s[8];
            #pragma unroll
            for (int j = 0; j < 8; j++) s[j] = sb2[cg + j];
            #pragma unroll 4
            for (int k = 0; k < 128; k++) {
                float tv = tS[lrow * TSTRIDE + k];
                float4 w0 = *reinterpret_cast<const float4*>(&sW2[k * NCLS + cg]);
                float4 w1 = *reinterpret_cast<const float4*>(&sW2[k * NCLS + cg + 4]);
                s[0] = fmaf(tv, w0.x, s[0]); s[1] = fmaf(tv, w0.y, s[1]);
                s[2] = fmaf(tv, w0.z, s[2]); s[3] = fmaf(tv, w0.w, s[3]);
                s[4] = fmaf(tv, w1.x, s[4]); s[5] = fmaf(tv, w1.y, s[5]);
                s[6] = fmaf(tv, w1.z, s[6]); s[7] = fmaf(tv, w1.w, s[7]);
            }
            *reinterpret_cast<float4*>(outp + (size_t)grow * NCLS + cg) =
                make_float4(s[0], s[1], s[2], s[3]);
            *reinterpret_cast<float4*>(outp + (size_t)grow * NCLS + cg + 4) =
                make_float4(s[4], s[5], s[6], s[7]);
        }
    }
}

// ---------------- launcher ----------------
extern "C" void kernel_launch(void* const* d_in, const int* in_sizes, int n_in,
                              void* d_out, int out_size) {
    const float* gene  = (const float*)d_in[0];
    const float* train = (const float*)d_in[1];
    const int*   esrc  = (const int*)d_in[2];
    const int*   edst  = (const int*)d_in[3];
    const float* W1n   = (const float*)d_in[4];
    const float* W1s   = (const float*)d_in[5];
    const float* b1    = (const float*)d_in[6];
    const float* W2n   = (const float*)d_in[7];
    const float* W2s   = (const float*)d_in[8];
    const float* b2    = (const float*)d_in[9];
    const float* Wc1   = (const float*)d_in[10];
    const float* bc1   = (const float*)d_in[11];
    const float* Wc2   = (const float*)d_in[12];
    const float* bc2   = (const float*)d_in[13];
    float* out = (float*)d_out;

    __half *train16, *agg16, *h1, *h2, *bt1s, *bt1n, *bt2s, *bt2n, *btc1;
    cudaGetSymbolAddress((void**)&train16, g_train16);
    cudaGetSymbolAddress((void**)&agg16,   g_agg16);
    cudaGetSymbolAddress((void**)&h1,      g_h1);
    cudaGetSymbolAddress((void**)&h2,      g_h2);
    cudaGetSymbolAddress((void**)&bt1s,    g_Bt1s);
    cudaGetSymbolAddress((void**)&bt1n,    g_Bt1n);
    cudaGetSymbolAddress((void**)&bt2s,    g_Bt2s);
    cudaGetSymbolAddress((void**)&bt2n,    g_Bt2n);
    cudaGetSymbolAddress((void**)&btc1,    g_Btc1);

    static cudaStream_t s2 = nullptr;
    static cudaEvent_t evFork = nullptr, evJoin = nullptr;
    static int init_done = 0;
    if (!init_done) {
        cudaFuncSetAttribute(mma_gemm_dual, cudaFuncAttributeMaxDynamicSharedMemorySize, SM_TOTAL);
        cudaStreamCreateWithFlags(&s2, cudaStreamNonBlocking);
        cudaEventCreateWithFlags(&evFork, cudaEventDisableTiming);
        cudaEventCreateWithFlags(&evJoin, cudaEventDisableTiming);
        init_done = 1;
    }

    // fork: side stream does weight transposes + train16 while main runs edge pipeline
    cudaEventRecord(evFork, 0);
    cudaStreamWaitEvent(s2, evFork, 0);
    {
        dim3 gp(512, 6);
        prep_side_kernel<<<gp, 256, 0, s2>>>(train, W1s, W1n, W2s, W2n, Wc1);
    }
    cudaEventRecord(evJoin, s2);

    {
        dim3 gp(296, 2);
        prep_main_kernel<<<gp, 256>>>(gene);
    }
    hist_kernel<<<NE / 1024, 256>>>(edst);
    scan_kernel<<<1, 1024>>>();
    scatter_kernel<<<NE / 1024, 256>>>(esrc, edst);
    agg_kernel<<<(NT + 7) / 8, 256>>>();

    // join before GEMMs (need weights + train16)
    cudaStreamWaitEvent(0, evJoin, 0);

    int gblk = (NT + 127) / 128;  // 157
    // h1 = relu(train @ W1_self + agg @ W1_neigh + b1)
    mma_gemm_dual<<<gblk, 256, SM_TOTAL>>>(train16, KP1, KP1, bt1s,
                                           agg16, HID, HID, bt1n, b1, h1, NT,
                                           nullptr, nullptr, nullptr, 0);
    // h2 = relu(h1 @ W2_self + agg @ W2_neigh + b2)
    mma_gemm_dual<<<gblk, 256, SM_TOTAL>>>(h1, HID, HID, bt2s,
                                           agg16, HID, HID, bt2n, b2, h2, NT,
                                           nullptr, nullptr, nullptr, 0);
    // out = relu(h2 @ Wc1 + bc1) @ Wc2 + bc2   (fused classifier)
    mma_gemm_dual<<<gblk, 256, SM_TOTAL>>>(h2, HID, HID, btc1,
                                           nullptr, HID, 0, nullptr, bc1, nullptr, NT,
                                           Wc2, bc2, out, 1);
}

// round 12
// speedup vs baseline: 1.1250x; 1.1250x over previous
#include <cuda_runtime.h>
#include <cuda_fp16.h>
#include <cstdint>

#define NG 2500
#define NT 20000
#define NE 640000
#define SRCD 128
#define DSTD 500
#define HID 128
#define OUTD 128
#define NCLS 16
#define KP1 512               // padded K for layer-1 self GEMM
#define SCAN_BLKS 20
#define SCAN_SPAN 1000        // SCAN_BLKS * SCAN_SPAN = NT

// ---------------- scratch (device globals; no allocation allowed) ----------------
__device__ int    g_cnt[NT];
__device__ int    g_rowstart[NT];
__device__ int    g_bsum[SCAN_BLKS];
__device__ int    g_pos[NE];
__device__ int    g_sorted[NE];
__device__ __half g_train16[(size_t)NT * KP1];
__device__ __half g_gene16[NG * SRCD];
__device__ __half g_agg16[(size_t)NT * HID];
__device__ __half g_h1[(size_t)NT * HID];
__device__ __half g_h2[(size_t)NT * OUTD];
// transposed weights, [N=128, Kpad] K-major, fp16, zero-padded
__device__ __half g_Bt1s[128 * KP1];
__device__ __half g_Bt1n[128 * 128];
__device__ __half g_Bt2s[128 * 128];
__device__ __half g_Bt2n[128 * 128];
__device__ __half g_Btc1[128 * 128];

__device__ __forceinline__ uint32_t smem_to_u32(const void* p) {
    uint32_t a;
    asm("{ .reg .u64 t; cvta.to.shared.u64 t, %1; cvt.u32.u64 %0, t; }" : "=r"(a) : "l"(p));
    return a;
}
__device__ __forceinline__ uint32_t h2u(__half2 h) { return *reinterpret_cast<uint32_t*>(&h); }

// ---------------- 1a) main-stream prep: gene fp16 cache + zero counters ----------------
__global__ void prep_main_kernel(const float* __restrict__ gene) {
    int stride = gridDim.x * blockDim.x;
    int t0 = blockIdx.x * blockDim.x + threadIdx.x;
    if (blockIdx.y == 0) {
        int N = NG * SRCD / 4;
        for (int i = t0; i < N; i += stride) {
            float4 v = reinterpret_cast<const float4*>(gene)[i];
            uint2 u;
            u.x = h2u(__floats2half2_rn(v.x, v.y));
            u.y = h2u(__floats2half2_rn(v.z, v.w));
            reinterpret_cast<uint2*>(g_gene16)[i] = u;
        }
    } else {
        for (int i = t0; i < NT; i += stride) g_cnt[i] = 0;
    }
}

// ---------------- 1b) side-stream prep: weight transposes + train fp16 pad ----------------
__global__ void prep_side_kernel(const float* __restrict__ train,
                                 const float* __restrict__ W1s, const float* __restrict__ W1n,
                                 const float* __restrict__ W2s, const float* __restrict__ W2n,
                                 const float* __restrict__ Wc1) {
    int task = blockIdx.y;
    int stride = gridDim.x * blockDim.x;
    int t0 = blockIdx.x * blockDim.x + threadIdx.x;
    if (task < 5) {
        const float* src; __half* dst; int K, Kpad;
        if      (task == 0) { src = W1s; dst = g_Bt1s; K = DSTD; Kpad = KP1; }
        else if (task == 1) { src = W1n; dst = g_Bt1n; K = HID;  Kpad = 128; }
        else if (task == 2) { src = W2s; dst = g_Bt2s; K = HID;  Kpad = 128; }
        else if (task == 3) { src = W2n; dst = g_Bt2n; K = HID;  Kpad = 128; }
        else                { src = Wc1; dst = g_Btc1; K = OUTD; Kpad = 128; }
        int N = 128 * Kpad;
        for (int i = t0; i < N; i += stride) {
            int n = i / Kpad, k = i % Kpad;
            dst[i] = (k < K) ? __float2half_rn(src[k * 128 + n]) : __half(0.f);
        }
    } else {
        // train [NT,500] fp32 -> [NT,512] fp16 zero-padded, 8 elems/thread
        int N = NT * (KP1 / 8);
        for (int i = t0; i < N; i += stride) {
            int r = i >> 6;
            int k0 = (i & 63) << 3;
            float f[8];
            #pragma unroll
            for (int j = 0; j < 8; j++) {
                int k = k0 + j;
                f[j] = (k < DSTD) ? train[(size_t)r * DSTD + k] : 0.f;
            }
            uint4 u;
            u.x = h2u(__floats2half2_rn(f[0], f[1]));
            u.y = h2u(__floats2half2_rn(f[2], f[3]));
            u.z = h2u(__floats2half2_rn(f[4], f[5]));
            u.w = h2u(__floats2half2_rn(f[6], f[7]));
            *reinterpret_cast<uint4*>(&g_train16[(size_t)r * KP1 + k0]) = u;
        }
    }
}

// ---------------- 2) histogram + within-row rank (ILP 4) ----------------
__global__ void hist_kernel(const int* __restrict__ edst) {
    int base = blockIdx.x * 1024 + threadIdx.x;
    int d0 = edst[base];
    int d1 = edst[base + 256];
    int d2 = edst[base + 512];
    int d3 = edst[base + 768];
    g_pos[base      ] = atomicAdd(&g_cnt[d0], 1);
    g_pos[base + 256] = atomicAdd(&g_cnt[d1], 1);
    g_pos[base + 512] = atomicAdd(&g_cnt[d2], 1);
    g_pos[base + 768] = atomicAdd(&g_cnt[d3], 1);
}

// ---------------- 3a) block-parallel scan, phase 1: per-block prefix + totals ----------
__global__ __launch_bounds__(1024) void scan1_kernel() {
    __shared__ int wsum[32];
    int b = blockIdx.x;
    int t = threadIdx.x, lane = t & 31, w = t >> 5;
    int i = b * SCAN_SPAN + t;
    int v = (t < SCAN_SPAN) ? g_cnt[i] : 0;
    int incl = v;
    #pragma unroll
    for (int d = 1; d < 32; d <<= 1) {
        int x = __shfl_up_sync(0xFFFFFFFFu, incl, d);
        if (lane >= d) incl += x;
    }
    if (lane == 31) wsum[w] = incl;
    __syncthreads();
    if (w == 0) {
        int x = wsum[lane];
        #pragma unroll
        for (int d = 1; d < 32; d <<= 1) {
            int y = __shfl_up_sync(0xFFFFFFFFu, x, d);
            if (lane >= d) x += y;
        }
        wsum[lane] = x;
    }
    __syncthreads();
    int excl = (w > 0 ? wsum[w - 1] : 0) + incl - v;
    if (t < SCAN_SPAN) g_rowstart[i] = excl;
    if (t == 0) g_bsum[b] = wsum[31];
}

// ---------------- 3b) phase 2: add preceding-block offsets ----------------
__global__ __launch_bounds__(1024) void scan2_kernel() {
    __shared__ int s_off;
    int b = blockIdx.x;
    int t = threadIdx.x;
    if (b == 0) return;
    if (t < 32) {
        int v = (t < b) ? g_bsum[t] : 0;
        #pragma unroll
        for (int d = 16; d > 0; d >>= 1) v += __shfl_down_sync(0xFFFFFFFFu, v, d);
        if (t == 0) s_off = v;
    }
    __syncthreads();
    if (t < SCAN_SPAN) g_rowstart[b * SCAN_SPAN + t] += s_off;
}

// ---------------- 4) pure scatter (no atomics, ILP 5) ----------------
__global__ void scatter_kernel(const int* __restrict__ esrc, const int* __restrict__ edst) {
    int base = blockIdx.x * 1280 + threadIdx.x;
    int d[5], p[5], s[5];
    #pragma unroll
    for (int j = 0; j < 5; j++) d[j] = edst[base + j * 256];
    #pragma unroll
    for (int j = 0; j < 5; j++) p[j] = g_pos[base + j * 256];
    #pragma unroll
    for (int j = 0; j < 5; j++) s[j] = esrc[base + j * 256];
    int r[5];
    #pragma unroll
    for (int j = 0; j < 5; j++) r[j] = g_rowstart[d[j]];
    #pragma unroll
    for (int j = 0; j < 5; j++) g_sorted[r[j] + p[j]] = s[j];
}

// ---------------- 5) mean aggregation from fp16 gene cache -> fp16 agg ----------------
__global__ void agg_kernel() {
    int d = blockIdx.x * 8 + (threadIdx.x >> 5);
    if (d >= NT) return;
    int lane = threadIdx.x & 31;
    int start = g_rowstart[d];
    int n = g_cnt[d];
    const uint2* G = reinterpret_cast<const uint2*>(g_gene16);

    float4 a0 = {0.f, 0.f, 0.f, 0.f}, a1 = a0, a2 = a0, a3 = a0;
    int e = 0;
    for (; e + 4 <= n; e += 4) {
        int s0 = g_sorted[start + e + 0];
        int s1 = g_sorted[start + e + 1];
        int s2 = g_sorted[start + e + 2];
        int s3 = g_sorted[start + e + 3];
        uint2 u0 = G[s0 * 32 + lane];
        uint2 u1 = G[s1 * 32 + lane];
        uint2 u2 = G[s2 * 32 + lane];
        uint2 u3 = G[s3 * 32 + lane];
        float2 f;
        f = __half22float2(*reinterpret_cast<__half2*>(&u0.x)); a0.x += f.x; a0.y += f.y;
        f = __half22float2(*reinterpret_cast<__half2*>(&u0.y)); a0.z += f.x; a0.w += f.y;
        f = __half22float2(*reinterpret_cast<__half2*>(&u1.x)); a1.x += f.x; a1.y += f.y;
        f = __half22float2(*reinterpret_cast<__half2*>(&u1.y)); a1.z += f.x; a1.w += f.y;
        f = __half22float2(*reinterpret_cast<__half2*>(&u2.x)); a2.x += f.x; a2.y += f.y;
        f = __half22float2(*reinterpret_cast<__half2*>(&u2.y)); a2.z += f.x; a2.w += f.y;
        f = __half22float2(*reinterpret_cast<__half2*>(&u3.x)); a3.x += f.x; a3.y += f.y;
        f = __half22float2(*reinterpret_cast<__half2*>(&u3.y)); a3.z += f.x; a3.w += f.y;
    }
    for (; e < n; e++) {
        int s = g_sorted[start + e];
        uint2 u = G[s * 32 + lane];
        float2 f;
        f = __half22float2(*reinterpret_cast<__half2*>(&u.x)); a0.x += f.x; a0.y += f.y;
        f = __half22float2(*reinterpret_cast<__half2*>(&u.y)); a0.z += f.x; a0.w += f.y;
    }
    float4 acc;
    acc.x = a0.x + a1.x + a2.x + a3.x;
    acc.y = a0.y + a1.y + a2.y + a3.y;
    acc.z = a0.z + a1.z + a2.z + a3.z;
    acc.w = a0.w + a1.w + a2.w + a3.w;
    float inv = 1.0f / fmaxf((float)n, 1.0f);
    uint2 u;
    u.x = h2u(__floats2half2_rn(acc.x * inv, acc.y * inv));
    u.y = h2u(__floats2half2_rn(acc.z * inv, acc.w * inv));
    reinterpret_cast<uint2*>(g_agg16)[(size_t)d * 32 + lane] = u;
}

// ---------------- 6) fp16 mma.sync dual GEMM (m16n8k16) + ldmatrix, cp.async 2-buf -------
#define KC    64                 // k-chunk (halves)
#define KPADH 72                 // smem row stride in halves
#define ABUFH (128 * KPADH)      // halves per buffer
#define SM_BIASF (2 * ABUFH)
#define SM_W2F   (SM_BIASF + 128)
#define SM_B2F   (SM_W2F + 2048)
#define SM_TOTAL ((SM_B2F + 16) * 4)
#define TSTRIDE  130

__global__ __launch_bounds__(256, 2)
void mma_gemm_dual(const __half* __restrict__ A1, int lda1, int K1, const __half* __restrict__ Bt1,
                   const __half* __restrict__ A2, int lda2, int K2, const __half* __restrict__ Bt2,
                   const float* __restrict__ bias, __half* __restrict__ C, int M,
                   const float* __restrict__ Wc2, const float* __restrict__ bc2,
                   float* __restrict__ outp, int fuse_cls) {
    extern __shared__ float smemf[];
    __half* As = reinterpret_cast<__half*>(smemf);
    __half* Bs = As + 2 * ABUFH;
    float* sbias = smemf + SM_BIASF;

    int tid = threadIdx.x;
    int wid = tid >> 5, lane = tid & 31;
    int wm = wid & 3, wn = wid >> 2;
    int g  = lane >> 2, tq = lane & 3;
    int row0 = blockIdx.x * 128;

    if (tid < 128) sbias[tid] = bias[tid];

    int nch1 = K1 / KC;
    int nch2 = K2 / KC;
    int nct  = nch1 + nch2;

    auto stage = [&](int c, int buf) {
        const __half* Ap; const __half* Bp; int lda, kb, k0;
        if (c < nch1) { Ap = A1; Bp = Bt1; lda = lda1; kb = K1; k0 = c * KC; }
        else          { Ap = A2; Bp = Bt2; lda = lda2; kb = K2; k0 = (c - nch1) * KC; }
        __half* Ad = As + buf * ABUFH;
        __half* Bd = Bs + buf * ABUFH;
        #pragma unroll
        for (int i = 0; i < 4; i++) {
            int idx = tid + i * 256;
            int r = idx >> 3, seg = idx & 7;
            int gr = row0 + r;
            int ok = gr < M;
            const __half* src = Ap + ((size_t)(ok ? gr : 0) * lda + k0 + seg * 8);
            uint32_t da = smem_to_u32(Ad + r * KPADH + seg * 8);
            asm volatile("cp.async.cg.shared.global [%0], [%1], 16, %2;"
                         :: "r"(da), "l"(src), "r"(ok ? 16 : 0));
            const __half* bsrc = Bp + ((size_t)r * kb + k0 + seg * 8);
            uint32_t db = smem_to_u32(Bd + r * KPADH + seg * 8);
            asm volatile("cp.async.cg.shared.global [%0], [%1], 16, %2;"
                         :: "r"(db), "l"(bsrc), "r"(16));
        }
        asm volatile("cp.async.commit_group;" ::: "memory");
    };

    float acc[2][8][4];
    #pragma unroll
    for (int mt = 0; mt < 2; mt++)
        #pragma unroll
        for (int nt = 0; nt < 8; nt++)
            #pragma unroll
            for (int q = 0; q < 4; q++) acc[mt][nt][q] = 0.f;

    int a_row = lane & 15;
    int a_koff = (lane >> 4) << 3;
    int b_row = (lane & 7) + ((lane >> 4) << 3);
    int b_koff = ((lane >> 3) & 1) << 3;

    stage(0, 0);

    #pragma unroll 1
    for (int c = 0; c < nct; c++) {
        int buf = c & 1;
        if (c + 1 < nct) {
            stage(c + 1, buf ^ 1);
            asm volatile("cp.async.wait_group 1;" ::: "memory");
        } else {
            asm volatile("cp.async.wait_group 0;" ::: "memory");
        }
        __syncthreads();

        uint32_t aAddr[2], bAddr[4];
        {
            uint32_t abase = smem_to_u32(As + buf * ABUFH);
            uint32_t bbase = smem_to_u32(Bs + buf * ABUFH);
            #pragma unroll
            for (int mt = 0; mt < 2; mt++)
                aAddr[mt] = abase + ((wm * 32 + mt * 16 + a_row) * KPADH + a_koff) * 2;
            #pragma unroll
            for (int q = 0; q < 4; q++)
                bAddr[q] = bbase + ((wn * 64 + q * 16 + b_row) * KPADH + b_koff) * 2;
        }

        #pragma unroll
        for (int ks = 0; ks < KC / 16; ks++) {
            int kb2 = ks * 32;
            uint32_t afr[2][4];
            #pragma unroll
            for (int mt = 0; mt < 2; mt++) {
                asm volatile("ldmatrix.sync.aligned.m8n8.x4.shared.b16 {%0,%1,%2,%3}, [%4];"
                             : "=r"(afr[mt][0]), "=r"(afr[mt][1]),
                               "=r"(afr[mt][2]), "=r"(afr[mt][3])
                             : "r"(aAddr[mt] + kb2));
            }
            uint32_t bfr[8][2];
            #pragma unroll
            for (int q = 0; q < 4; q++) {
                asm volatile("ldmatrix.sync.aligned.m8n8.x4.shared.b16 {%0,%1,%2,%3}, [%4];"
                             : "=r"(bfr[2 * q][0]), "=r"(bfr[2 * q][1]),
                               "=r"(bfr[2 * q + 1][0]), "=r"(bfr[2 * q + 1][1])
                             : "r"(bAddr[q] + kb2));
            }
            #pragma unroll
            for (int mt = 0; mt < 2; mt++)
                #pragma unroll
                for (int nt = 0; nt < 8; nt++) {
                    asm volatile(
                        "mma.sync.aligned.m16n8k16.row.col.f32.f16.f16.f32 "
                        "{%0,%1,%2,%3}, {%4,%5,%6,%7}, {%8,%9}, {%0,%1,%2,%3};"
                        : "+f"(acc[mt][nt][0]), "+f"(acc[mt][nt][1]),
                          "+f"(acc[mt][nt][2]), "+f"(acc[mt][nt][3])
                        : "r"(afr[mt][0]), "r"(afr[mt][1]), "r"(afr[mt][2]), "r"(afr[mt][3]),
                          "r"(bfr[nt][0]), "r"(bfr[nt][1]));
                }
        }
        __syncthreads();
    }

    if (!fuse_cls) {
        #pragma unroll
        for (int mt = 0; mt < 2; mt++) {
            int r1 = row0 + wm * 32 + mt * 16 + g;
            int r2 = r1 + 8;
            #pragma unroll
            for (int nt = 0; nt < 8; nt++) {
                int col = wn * 64 + nt * 8 + tq * 2;
                float b0 = sbias[col], b1 = sbias[col + 1];
                float v10 = fmaxf(acc[mt][nt][0] + b0, 0.f);
                float v11 = fmaxf(acc[mt][nt][1] + b1, 0.f);
                float v20 = fmaxf(acc[mt][nt][2] + b0, 0.f);
                float v21 = fmaxf(acc[mt][nt][3] + b1, 0.f);
                if (r1 < M)
                    *reinterpret_cast<uint32_t*>(C + (size_t)r1 * 128 + col) =
                        h2u(__floats2half2_rn(v10, v11));
                if (r2 < M)
                    *reinterpret_cast<uint32_t*>(C + (size_t)r2 * 128 + col) =
                        h2u(__floats2half2_rn(v20, v21));
            }
        }
    } else {
        float* tS  = smemf;
        float* sW2 = smemf + SM_W2F;
        float* sb2 = smemf + SM_B2F;
        for (int i = tid; i < 128 * NCLS; i += 256) sW2[i] = Wc2[i];
        if (tid < NCLS) sb2[tid] = bc2[tid];
        #pragma unroll
        for (int mt = 0; mt < 2; mt++) {
            int lr1 = wm * 32 + mt * 16 + g;
            int lr2 = lr1 + 8;
            #pragma unroll
            for (int nt = 0; nt < 8; nt++) {
                int col = wn * 64 + nt * 8 + tq * 2;
                float b0 = sbias[col], b1 = sbias[col + 1];
                tS[lr1 * TSTRIDE + col]     = fmaxf(acc[mt][nt][0] + b0, 0.f);
                tS[lr1 * TSTRIDE + col + 1] = fmaxf(acc[mt][nt][1] + b1, 0.f);
                tS[lr2 * TSTRIDE + col]     = fmaxf(acc[mt][nt][2] + b0, 0.f);
                tS[lr2 * TSTRIDE + col + 1] = fmaxf(acc[mt][nt][3] + b1, 0.f);
            }
        }
        __syncthreads();
        int lrow = tid >> 1;
        int cg = (tid & 1) * 8;
        int grow = row0 + lrow;
        if (grow < M) {
            float s[8];
            #pragma unroll
            for (int j = 0; j < 8; j++) s[j] = sb2[cg + j];
            #pragma unroll 4
            for (int k = 0; k < 128; k++) {
                float tv = tS[lrow * TSTRIDE + k];
                float4 w0 = *reinterpret_cast<const float4*>(&sW2[k * NCLS + cg]);
                float4 w1 = *reinterpret_cast<const float4*>(&sW2[k * NCLS + cg + 4]);
                s[0] = fmaf(tv, w0.x, s[0]); s[1] = fmaf(tv, w0.y, s[1]);
                s[2] = fmaf(tv, w0.z, s[2]); s[3] = fmaf(tv, w0.w, s[3]);
                s[4] = fmaf(tv, w1.x, s[4]); s[5] = fmaf(tv, w1.y, s[5]);
                s[6] = fmaf(tv, w1.z, s[6]); s[7] = fmaf(tv, w1.w, s[7]);
            }
            *reinterpret_cast<float4*>(outp + (size_t)grow * NCLS + cg) =
                make_float4(s[0], s[1], s[2], s[3]);
            *reinterpret_cast<float4*>(outp + (size_t)grow * NCLS + cg + 4) =
                make_float4(s[4], s[5], s[6], s[7]);
        }
    }
}

// ---------------- launcher ----------------
extern "C" void kernel_launch(void* const* d_in, const int* in_sizes, int n_in,
                              void* d_out, int out_size) {
    const float* gene  = (const float*)d_in[0];
    const float* train = (const float*)d_in[1];
    const int*   esrc  = (const int*)d_in[2];
    const int*   edst  = (const int*)d_in[3];
    const float* W1n   = (const float*)d_in[4];
    const float* W1s   = (const float*)d_in[5];
    const float* b1    = (const float*)d_in[6];
    const float* W2n   = (const float*)d_in[7];
    const float* W2s   = (const float*)d_in[8];
    const float* b2    = (const float*)d_in[9];
    const float* Wc1   = (const float*)d_in[10];
    const float* bc1   = (const float*)d_in[11];
    const float* Wc2   = (const float*)d_in[12];
    const float* bc2   = (const float*)d_in[13];
    float* out = (float*)d_out;

    __half *train16, *agg16, *h1, *h2, *bt1s, *bt1n, *bt2s, *bt2n, *btc1;
    cudaGetSymbolAddress((void**)&train16, g_train16);
    cudaGetSymbolAddress((void**)&agg16,   g_agg16);
    cudaGetSymbolAddress((void**)&h1,      g_h1);
    cudaGetSymbolAddress((void**)&h2,      g_h2);
    cudaGetSymbolAddress((void**)&bt1s,    g_Bt1s);
    cudaGetSymbolAddress((void**)&bt1n,    g_Bt1n);
    cudaGetSymbolAddress((void**)&bt2s,    g_Bt2s);
    cudaGetSymbolAddress((void**)&bt2n,    g_Bt2n);
    cudaGetSymbolAddress((void**)&btc1,    g_Btc1);

    static cudaStream_t s2 = nullptr;
    static cudaEvent_t evFork = nullptr, evJoin = nullptr;
    static int init_done = 0;
    if (!init_done) {
        cudaFuncSetAttribute(mma_gemm_dual, cudaFuncAttributeMaxDynamicSharedMemorySize, SM_TOTAL);
        cudaStreamCreateWithFlags(&s2, cudaStreamNonBlocking);
        cudaEventCreateWithFlags(&evFork, cudaEventDisableTiming);
        cudaEventCreateWithFlags(&evJoin, cudaEventDisableTiming);
        init_done = 1;
    }

    // fork: side stream does weight transposes + train16 while main runs edge pipeline
    cudaEventRecord(evFork, 0);
    cudaStreamWaitEvent(s2, evFork, 0);
    {
        dim3 gp(512, 6);
        prep_side_kernel<<<gp, 256, 0, s2>>>(train, W1s, W1n, W2s, W2n, Wc1);
    }
    cudaEventRecord(evJoin, s2);

    {
        dim3 gp(296, 2);
        prep_main_kernel<<<gp, 256>>>(gene);
    }
    hist_kernel<<<NE / 1024, 256>>>(edst);
    scan1_kernel<<<SCAN_BLKS, 1024>>>();
    scan2_kernel<<<SCAN_BLKS, 1024>>>();
    scatter_kernel<<<NE / 1280, 256>>>(esrc, edst);
    agg_kernel<<<(NT + 7) / 8, 256>>>();

    // join before GEMMs (need weights + train16)
    cudaStreamWaitEvent(0, evJoin, 0);

    int gblk = (NT + 127) / 128;  // 157
    // h1 = relu(train @ W1_self + agg @ W1_neigh + b1)
    mma_gemm_dual<<<gblk, 256, SM_TOTAL>>>(train16, KP1, KP1, bt1s,
                                           agg16, HID, HID, bt1n, b1, h1, NT,
                                           nullptr, nullptr, nullptr, 0);
    // h2 = relu(h1 @ W2_self + agg @ W2_neigh + b2)
    mma_gemm_dual<<<gblk, 256, SM_TOTAL>>>(h1, HID, HID, bt2s,
                                           agg16, HID, HID, bt2n, b2, h2, NT,
                                           nullptr, nullptr, nullptr, 0);
    // out = relu(h2 @ Wc1 + bc1) @ Wc2 + bc2   (fused classifier)
    mma_gemm_dual<<<gblk, 256, SM_TOTAL>>>(h2, HID, HID, btc1,
                                           nullptr, HID, 0, nullptr, bc1, nullptr, NT,
                                           Wc2, bc2, out, 1);
}

// round 14
// speedup vs baseline: 1.1770x; 1.0462x over previous
#include <cuda_runtime.h>
#include <cuda_fp16.h>
#include <cstdint>

#define NG 2500
#define NT 20000
#define NE 640000
#define SRCD 128
#define DSTD 500
#define HID 128
#define OUTD 128
#define NCLS 16
#define KP1 512               // padded K for layer-1 self GEMM
#define SCAN_BLKS 20
#define SCAN_SPAN 1000        // SCAN_BLKS * SCAN_SPAN = NT

// ---------------- scratch (device globals; no allocation allowed) ----------------
__device__ int    g_cnt[NT];
__device__ int    g_rowstart[NT];     // per-block exclusive prefix (local)
__device__ int    g_bsum[SCAN_BLKS];
__device__ int    g_boff[SCAN_BLKS];  // exclusive prefix of block totals
__device__ int    g_pos[NE];
__device__ int    g_sorted[NE];
__device__ float  g_h1f[(size_t)NT * HID];   // fp32 partial: train @ W1s
__device__ __half g_train16[(size_t)NT * KP1];
__device__ __half g_gene16[NG * SRCD];
__device__ __half g_agg16[(size_t)NT * HID];
__device__ __half g_h1[(size_t)NT * HID];
__device__ __half g_h2[(size_t)NT * OUTD];
// transposed weights, [N=128, Kpad] K-major, fp16, zero-padded
__device__ __half g_Bt1s[128 * KP1];
__device__ __half g_Bt1n[128 * 128];
__device__ __half g_Bt2s[128 * 128];
__device__ __half g_Bt2n[128 * 128];
__device__ __half g_Btc1[128 * 128];

__device__ __forceinline__ uint32_t smem_to_u32(const void* p) {
    uint32_t a;
    asm("{ .reg .u64 t; cvta.to.shared.u64 t, %1; cvt.u32.u64 %0, t; }" : "=r"(a) : "l"(p));
    return a;
}
__device__ __forceinline__ uint32_t h2u(__half2 h) { return *reinterpret_cast<uint32_t*>(&h); }

// ---------------- 1a) main-stream prep: gene fp16 cache + zero counters ----------------
__global__ void prep_main_kernel(const float* __restrict__ gene) {
    int stride = gridDim.x * blockDim.x;
    int t0 = blockIdx.x * blockDim.x + threadIdx.x;
    if (blockIdx.y == 0) {
        int N = NG * SRCD / 4;
        for (int i = t0; i < N; i += stride) {
            float4 v = reinterpret_cast<const float4*>(gene)[i];
            uint2 u;
            u.x = h2u(__floats2half2_rn(v.x, v.y));
            u.y = h2u(__floats2half2_rn(v.z, v.w));
            reinterpret_cast<uint2*>(g_gene16)[i] = u;
        }
    } else {
        for (int i = t0; i < NT; i += stride) g_cnt[i] = 0;
    }
}

// ---------------- 1b) side-stream prep: weight transposes + train fp16 pad ----------------
__global__ void prep_side_kernel(const float* __restrict__ train,
                                 const float* __restrict__ W1s, const float* __restrict__ W1n,
                                 const float* __restrict__ W2s, const float* __restrict__ W2n,
                                 const float* __restrict__ Wc1) {
    int task = blockIdx.y;
    int stride = gridDim.x * blockDim.x;
    int t0 = blockIdx.x * blockDim.x + threadIdx.x;
    if (task < 5) {
        const float* src; __half* dst; int K, Kpad;
        if      (task == 0) { src = W1s; dst = g_Bt1s; K = DSTD; Kpad = KP1; }
        else if (task == 1) { src = W1n; dst = g_Bt1n; K = HID;  Kpad = 128; }
        else if (task == 2) { src = W2s; dst = g_Bt2s; K = HID;  Kpad = 128; }
        else if (task == 3) { src = W2n; dst = g_Bt2n; K = HID;  Kpad = 128; }
        else                { src = Wc1; dst = g_Btc1; K = OUTD; Kpad = 128; }
        int N = 128 * Kpad;
        for (int i = t0; i < N; i += stride) {
            int n = i / Kpad, k = i % Kpad;
            dst[i] = (k < K) ? __float2half_rn(src[k * 128 + n]) : __half(0.f);
        }
    } else {
        // train [NT,500] fp32 -> [NT,512] fp16 zero-padded, 8 elems/thread
        int N = NT * (KP1 / 8);
        for (int i = t0; i < N; i += stride) {
            int r = i >> 6;
            int k0 = (i & 63) << 3;
            float f[8];
            #pragma unroll
            for (int j = 0; j < 8; j++) {
                int k = k0 + j;
                f[j] = (k < DSTD) ? train[(size_t)r * DSTD + k] : 0.f;
            }
            uint4 u;
            u.x = h2u(__floats2half2_rn(f[0], f[1]));
            u.y = h2u(__floats2half2_rn(f[2], f[3]));
            u.z = h2u(__floats2half2_rn(f[4], f[5]));
            u.w = h2u(__floats2half2_rn(f[6], f[7]));
            *reinterpret_cast<uint4*>(&g_train16[(size_t)r * KP1 + k0]) = u;
        }
    }
}

// ---------------- 2) histogram + within-row rank (ILP 4) ----------------
__global__ void hist_kernel(const int* __restrict__ edst) {
    int base = blockIdx.x * 1024 + threadIdx.x;
    int d0 = edst[base];
    int d1 = edst[base + 256];
    int d2 = edst[base + 512];
    int d3 = edst[base + 768];
    g_pos[base      ] = atomicAdd(&g_cnt[d0], 1);
    g_pos[base + 256] = atomicAdd(&g_cnt[d1], 1);
    g_pos[base + 512] = atomicAdd(&g_cnt[d2], 1);
    g_pos[base + 768] = atomicAdd(&g_cnt[d3], 1);
}

// ---------------- 3a) block-parallel scan, phase 1: per-block local prefix + totals ------
__global__ __launch_bounds__(1024) void scan1_kernel() {
    __shared__ int wsum[32];
    int b = blockIdx.x;
    int t = threadIdx.x, lane = t & 31, w = t >> 5;
    int i = b * SCAN_SPAN + t;
    int v = (t < SCAN_SPAN) ? g_cnt[i] : 0;
    int incl = v;
    #pragma unroll
    for (int d = 1; d < 32; d <<= 1) {
        int x = __shfl_up_sync(0xFFFFFFFFu, incl, d);
        if (lane >= d) incl += x;
    }
    if (lane == 31) wsum[w] = incl;
    __syncthreads();
    if (w == 0) {
        int x = wsum[lane];
        #pragma unroll
        for (int d = 1; d < 32; d <<= 1) {
            int y = __shfl_up_sync(0xFFFFFFFFu, x, d);
            if (lane >= d) x += y;
        }
        wsum[lane] = x;
    }
    __syncthreads();
    int excl = (w > 0 ? wsum[w - 1] : 0) + incl - v;
    if (t < SCAN_SPAN) g_rowstart[i] = excl;
    if (t == 0) g_bsum[b] = wsum[31];
}

// ---------------- 3b) phase 2: tiny block-offset scan (1 warp) ----------------
__global__ void scan2b_kernel() {
    int t = threadIdx.x;   // 32 threads
    int v = (t < SCAN_BLKS) ? g_bsum[t] : 0;
    int incl = v;
    #pragma unroll
    for (int d = 1; d < 32; d <<= 1) {
        int x = __shfl_up_sync(0xFFFFFFFFu, incl, d);
        if (t >= d) incl += x;
    }
    if (t < SCAN_BLKS) g_boff[t] = incl - v;
}

// ---------------- 4) pure scatter (no atomics, ILP 5, inline block offset) -------------
__global__ void scatter_kernel(const int* __restrict__ esrc, const int* __restrict__ edst) {
    int base = blockIdx.x * 1280 + threadIdx.x;
    int d[5], p[5], s[5];
    #pragma unroll
    for (int j = 0; j < 5; j++) d[j] = edst[base + j * 256];
    #pragma unroll
    for (int j = 0; j < 5; j++) p[j] = g_pos[base + j * 256];
    #pragma unroll
    for (int j = 0; j < 5; j++) s[j] = esrc[base + j * 256];
    int r[5];
    #pragma unroll
    for (int j = 0; j < 5; j++) r[j] = g_rowstart[d[j]] + g_boff[d[j] / SCAN_SPAN];
    #pragma unroll
    for (int j = 0; j < 5; j++) g_sorted[r[j] + p[j]] = s[j];
}

// ---------------- 5) mean aggregation from fp16 gene cache -> fp16 agg ----------------
__global__ void agg_kernel() {
    int d = blockIdx.x * 8 + (threadIdx.x >> 5);
    if (d >= NT) return;
    int lane = threadIdx.x & 31;
    int start = g_rowstart[d] + g_boff[d / SCAN_SPAN];
    int n = g_cnt[d];
    const uint2* G = reinterpret_cast<const uint2*>(g_gene16);

    float4 a0 = {0.f, 0.f, 0.f, 0.f}, a1 = a0, a2 = a0, a3 = a0;
    int e = 0;
    for (; e + 4 <= n; e += 4) {
        int s0 = g_sorted[start + e + 0];
        int s1 = g_sorted[start + e + 1];
        int s2 = g_sorted[start + e + 2];
        int s3 = g_sorted[start + e + 3];
        uint2 u0 = G[s0 * 32 + lane];
        uint2 u1 = G[s1 * 32 + lane];
        uint2 u2 = G[s2 * 32 + lane];
        uint2 u3 = G[s3 * 32 + lane];
        float2 f;
        f = __half22float2(*reinterpret_cast<__half2*>(&u0.x)); a0.x += f.x; a0.y += f.y;
        f = __half22float2(*reinterpret_cast<__half2*>(&u0.y)); a0.z += f.x; a0.w += f.y;
        f = __half22float2(*reinterpret_cast<__half2*>(&u1.x)); a1.x += f.x; a1.y += f.y;
        f = __half22float2(*reinterpret_cast<__half2*>(&u1.y)); a1.z += f.x; a1.w += f.y;
        f = __half22float2(*reinterpret_cast<__half2*>(&u2.x)); a2.x += f.x; a2.y += f.y;
        f = __half22float2(*reinterpret_cast<__half2*>(&u2.y)); a2.z += f.x; a2.w += f.y;
        f = __half22float2(*reinterpret_cast<__half2*>(&u3.x)); a3.x += f.x; a3.y += f.y;
        f = __half22float2(*reinterpret_cast<__half2*>(&u3.y)); a3.z += f.x; a3.w += f.y;
    }
    for (; e < n; e++) {
        int s = g_sorted[start + e];
        uint2 u = G[s * 32 + lane];
        float2 f;
        f = __half22float2(*reinterpret_cast<__half2*>(&u.x)); a0.x += f.x; a0.y += f.y;
        f = __half22float2(*reinterpret_cast<__half2*>(&u.y)); a0.z += f.x; a0.w += f.y;
    }
    float4 acc;
    acc.x = a0.x + a1.x + a2.x + a3.x;
    acc.y = a0.y + a1.y + a2.y + a3.y;
    acc.z = a0.z + a1.z + a2.z + a3.z;
    acc.w = a0.w + a1.w + a2.w + a3.w;
    float inv = 1.0f / fmaxf((float)n, 1.0f);
    uint2 u;
    u.x = h2u(__floats2half2_rn(acc.x * inv, acc.y * inv));
    u.y = h2u(__floats2half2_rn(acc.z * inv, acc.w * inv));
    reinterpret_cast<uint2*>(g_agg16)[(size_t)d * 32 + lane] = u;
}

// ---------------- 6) fp16 mma.sync dual GEMM (m16n8k16) + ldmatrix, cp.async 2-buf -------
// out_mode: 0 = bias+relu(+Pin) -> fp16 C;  1 = fused classifier -> fp32 outp;
//           2 = raw fp32 partial -> outp
#define KC    64                 // k-chunk (halves)
#define KPADH 72                 // smem row stride in halves
#define ABUFH (128 * KPADH)      // halves per buffer
#define SM_BIASF (2 * ABUFH)
#define SM_W2F   (SM_BIASF + 128)
#define SM_B2F   (SM_W2F + 2048)
#define SM_TOTAL ((SM_B2F + 16) * 4)
#define TSTRIDE  130

__global__ __launch_bounds__(256, 2)
void mma_gemm_dual(const __half* __restrict__ A1, int lda1, int K1, const __half* __restrict__ Bt1,
                   const __half* __restrict__ A2, int lda2, int K2, const __half* __restrict__ Bt2,
                   const float* __restrict__ bias, __half* __restrict__ C, int M,
                   const float* __restrict__ Wc2, const float* __restrict__ bc2,
                   float* __restrict__ outp, const float* __restrict__ Pin, int out_mode) {
    extern __shared__ float smemf[];
    __half* As = reinterpret_cast<__half*>(smemf);
    __half* Bs = As + 2 * ABUFH;
    float* sbias = smemf + SM_BIASF;

    int tid = threadIdx.x;
    int wid = tid >> 5, lane = tid & 31;
    int wm = wid & 3, wn = wid >> 2;
    int g  = lane >> 2, tq = lane & 3;
    int row0 = blockIdx.x * 128;

    if (tid < 128) sbias[tid] = bias[tid];

    int nch1 = K1 / KC;
    int nch2 = K2 / KC;
    int nct  = nch1 + nch2;

    auto stage = [&](int c, int buf) {
        const __half* Ap; const __half* Bp; int lda, kb, k0;
        if (c < nch1) { Ap = A1; Bp = Bt1; lda = lda1; kb = K1; k0 = c * KC; }
        else          { Ap = A2; Bp = Bt2; lda = lda2; kb = K2; k0 = (c - nch1) * KC; }
        __half* Ad = As + buf * ABUFH;
        __half* Bd = Bs + buf * ABUFH;
        #pragma unroll
        for (int i = 0; i < 4; i++) {
            int idx = tid + i * 256;
            int r = idx >> 3, seg = idx & 7;
            int gr = row0 + r;
            int ok = gr < M;
            const __half* src = Ap + ((size_t)(ok ? gr : 0) * lda + k0 + seg * 8);
            uint32_t da = smem_to_u32(Ad + r * KPADH + seg * 8);
            asm volatile("cp.async.cg.shared.global [%0], [%1], 16, %2;"
                         :: "r"(da), "l"(src), "r"(ok ? 16 : 0));
            const __half* bsrc = Bp + ((size_t)r * kb + k0 + seg * 8);
            uint32_t db = smem_to_u32(Bd + r * KPADH + seg * 8);
            asm volatile("cp.async.cg.shared.global [%0], [%1], 16, %2;"
                         :: "r"(db), "l"(bsrc), "r"(16));
        }
        asm volatile("cp.async.commit_group;" ::: "memory");
    };

    float acc[2][8][4];
    #pragma unroll
    for (int mt = 0; mt < 2; mt++)
        #pragma unroll
        for (int nt = 0; nt < 8; nt++)
            #pragma unroll
            for (int q = 0; q < 4; q++) acc[mt][nt][q] = 0.f;

    int a_row = lane & 15;
    int a_koff = (lane >> 4) << 3;
    int b_row = (lane & 7) + ((lane >> 4) << 3);
    int b_koff = ((lane >> 3) & 1) << 3;

    stage(0, 0);

    #pragma unroll 1
    for (int c = 0; c < nct; c++) {
        int buf = c & 1;
        if (c + 1 < nct) {
            stage(c + 1, buf ^ 1);
            asm volatile("cp.async.wait_group 1;" ::: "memory");
        } else {
            asm volatile("cp.async.wait_group 0;" ::: "memory");
        }
        __syncthreads();

        uint32_t aAddr[2], bAddr[4];
        {
            uint32_t abase = smem_to_u32(As + buf * ABUFH);
            uint32_t bbase = smem_to_u32(Bs + buf * ABUFH);
            #pragma unroll
            for (int mt = 0; mt < 2; mt++)
                aAddr[mt] = abase + ((wm * 32 + mt * 16 + a_row) * KPADH + a_koff) * 2;
            #pragma unroll
            for (int q = 0; q < 4; q++)
                bAddr[q] = bbase + ((wn * 64 + q * 16 + b_row) * KPADH + b_koff) * 2;
        }

        #pragma unroll
        for (int ks = 0; ks < KC / 16; ks++) {
            int kb2 = ks * 32;
            uint32_t afr[2][4];
            #pragma unroll
            for (int mt = 0; mt < 2; mt++) {
                asm volatile("ldmatrix.sync.aligned.m8n8.x4.shared.b16 {%0,%1,%2,%3}, [%4];"
                             : "=r"(afr[mt][0]), "=r"(afr[mt][1]),
                               "=r"(afr[mt][2]), "=r"(afr[mt][3])
                             : "r"(aAddr[mt] + kb2));
            }
            uint32_t bfr[8][2];
            #pragma unroll
            for (int q = 0; q < 4; q++) {
                asm volatile("ldmatrix.sync.aligned.m8n8.x4.shared.b16 {%0,%1,%2,%3}, [%4];"
                             : "=r"(bfr[2 * q][0]), "=r"(bfr[2 * q][1]),
                               "=r"(bfr[2 * q + 1][0]), "=r"(bfr[2 * q + 1][1])
                             : "r"(bAddr[q] + kb2));
            }
            #pragma unroll
            for (int mt = 0; mt < 2; mt++)
                #pragma unroll
                for (int nt = 0; nt < 8; nt++) {
                    asm volatile(
                        "mma.sync.aligned.m16n8k16.row.col.f32.f16.f16.f32 "
                        "{%0,%1,%2,%3}, {%4,%5,%6,%7}, {%8,%9}, {%0,%1,%2,%3};"
                        : "+f"(acc[mt][nt][0]), "+f"(acc[mt][nt][1]),
                          "+f"(acc[mt][nt][2]), "+f"(acc[mt][nt][3])
                        : "r"(afr[mt][0]), "r"(afr[mt][1]), "r"(afr[mt][2]), "r"(afr[mt][3]),
                          "r"(bfr[nt][0]), "r"(bfr[nt][1]));
                }
        }
        __syncthreads();
    }

    if (out_mode == 2) {
        // raw fp32 partial store
        #pragma unroll
        for (int mt = 0; mt < 2; mt++) {
            int r1 = row0 + wm * 32 + mt * 16 + g;
            int r2 = r1 + 8;
            #pragma unroll
            for (int nt = 0; nt < 8; nt++) {
                int col = wn * 64 + nt * 8 + tq * 2;
                if (r1 < M)
                    *reinterpret_cast<float2*>(outp + (size_t)r1 * 128 + col) =
                        make_float2(acc[mt][nt][0], acc[mt][nt][1]);
                if (r2 < M)
                    *reinterpret_cast<float2*>(outp + (size_t)r2 * 128 + col) =
                        make_float2(acc[mt][nt][2], acc[mt][nt][3]);
            }
        }
    } else if (out_mode == 0) {
        // bias + optional partial add + relu -> fp16 C
        #pragma unroll
        for (int mt = 0; mt < 2; mt++) {
            int r1 = row0 + wm * 32 + mt * 16 + g;
            int r2 = r1 + 8;
            #pragma unroll
            for (int nt = 0; nt < 8; nt++) {
                int col = wn * 64 + nt * 8 + tq * 2;
                float b0 = sbias[col], b1 = sbias[col + 1];
                float v10 = acc[mt][nt][0] + b0, v11 = acc[mt][nt][1] + b1;
                float v20 = acc[mt][nt][2] + b0, v21 = acc[mt][nt][3] + b1;
                if (Pin) {
                    if (r1 < M) {
                        float2 p1 = *reinterpret_cast<const float2*>(Pin + (size_t)r1 * 128 + col);
                        v10 += p1.x; v11 += p1.y;
                    }
                    if (r2 < M) {
                        float2 p2 = *reinterpret_cast<const float2*>(Pin + (size_t)r2 * 128 + col);
                        v20 += p2.x; v21 += p2.y;
                    }
                }
                v10 = fmaxf(v10, 0.f); v11 = fmaxf(v11, 0.f);
                v20 = fmaxf(v20, 0.f); v21 = fmaxf(v21, 0.f);
                if (r1 < M)
                    *reinterpret_cast<uint32_t*>(C + (size_t)r1 * 128 + col) =
                        h2u(__floats2half2_rn(v10, v11));
                if (r2 < M)
                    *reinterpret_cast<uint32_t*>(C + (size_t)r2 * 128 + col) =
                        h2u(__floats2half2_rn(v20, v21));
            }
        }
    } else {
        // fused classifier
        float* tS  = smemf;
        float* sW2 = smemf + SM_W2F;
        float* sb2 = smemf + SM_B2F;
        for (int i = tid; i < 128 * NCLS; i += 256) sW2[i] = Wc2[i];
        if (tid < NCLS) sb2[tid] = bc2[tid];
        #pragma unroll
        for (int mt = 0; mt < 2; mt++) {
            int lr1 = wm * 32 + mt * 16 + g;
            int lr2 = lr1 + 8;
            #pragma unroll
            for (int nt = 0; nt < 8; nt++) {
                int col = wn * 64 + nt * 8 + tq * 2;
                float b0 = sbias[col], b1 = sbias[col + 1];
                tS[lr1 * TSTRIDE + col]     = fmaxf(acc[mt][nt][0] + b0, 0.f);
                tS[lr1 * TSTRIDE + col + 1] = fmaxf(acc[mt][nt][1] + b1, 0.f);
                tS[lr2 * TSTRIDE + col]     = fmaxf(acc[mt][nt][2] + b0, 0.f);
                tS[lr2 * TSTRIDE + col + 1] = fmaxf(acc[mt][nt][3] + b1, 0.f);
            }
        }
        __syncthreads();
        int lrow = tid >> 1;
        int cg = (tid & 1) * 8;
        int grow = row0 + lrow;
        if (grow < M) {
            float s[8];
            #pragma unroll
            for (int j = 0; j < 8; j++) s[j] = sb2[cg + j];
            #pragma unroll 4
            for (int k = 0; k < 128; k++) {
                float tv = tS[lrow * TSTRIDE + k];
                float4 w0 = *reinterpret_cast<const float4*>(&sW2[k * NCLS + cg]);
                float4 w1 = *reinterpret_cast<const float4*>(&sW2[k * NCLS + cg + 4]);
                s[0] = fmaf(tv, w0.x, s[0]); s[1] = fmaf(tv, w0.y, s[1]);
                s[2] = fmaf(tv, w0.z, s[2]); s[3] = fmaf(tv, w0.w, s[3]);
                s[4] = fmaf(tv, w1.x, s[4]); s[5] = fmaf(tv, w1.y, s[5]);
                s[6] = fmaf(tv, w1.z, s[6]); s[7] = fmaf(tv, w1.w, s[7]);
            }
            *reinterpret_cast<float4*>(outp + (size_t)grow * NCLS + cg) =
                make_float4(s[0], s[1], s[2], s[3]);
            *reinterpret_cast<float4*>(outp + (size_t)grow * NCLS + cg + 4) =
                make_float4(s[4], s[5], s[6], s[7]);
        }
    }
}

// ---------------- launcher ----------------
extern "C" void kernel_launch(void* const* d_in, const int* in_sizes, int n_in,
                              void* d_out, int out_size) {
    const float* gene  = (const float*)d_in[0];
    const float* train = (const float*)d_in[1];
    const int*   esrc  = (const int*)d_in[2];
    const int*   edst  = (const int*)d_in[3];
    const float* W1n   = (const float*)d_in[4];
    const float* W1s   = (const float*)d_in[5];
    const float* b1    = (const float*)d_in[6];
    const float* W2n   = (const float*)d_in[7];
    const float* W2s   = (const float*)d_in[8];
    const float* b2    = (const float*)d_in[9];
    const float* Wc1   = (const float*)d_in[10];
    const float* bc1   = (const float*)d_in[11];
    const float* Wc2   = (const float*)d_in[12];
    const float* bc2   = (const float*)d_in[13];
    float* out = (float*)d_out;

    __half *train16, *agg16, *h1, *h2, *bt1s, *bt1n, *bt2s, *bt2n, *btc1;
    float* h1f;
    cudaGetSymbolAddress((void**)&train16, g_train16);
    cudaGetSymbolAddress((void**)&agg16,   g_agg16);
    cudaGetSymbolAddress((void**)&h1,      g_h1);
    cudaGetSymbolAddress((void**)&h2,      g_h2);
    cudaGetSymbolAddress((void**)&h1f,     g_h1f);
    cudaGetSymbolAddress((void**)&bt1s,    g_Bt1s);
    cudaGetSymbolAddress((void**)&bt1n,    g_Bt1n);
    cudaGetSymbolAddress((void**)&bt2s,    g_Bt2s);
    cudaGetSymbolAddress((void**)&bt2n,    g_Bt2n);
    cudaGetSymbolAddress((void**)&btc1,    g_Btc1);

    static cudaStream_t s2 = nullptr;
    static cudaEvent_t evFork = nullptr, evJoin = nullptr;
    static int init_done = 0;
    if (!init_done) {
        cudaFuncSetAttribute(mma_gemm_dual, cudaFuncAttributeMaxDynamicSharedMemorySize, SM_TOTAL);
        cudaStreamCreateWithFlags(&s2, cudaStreamNonBlocking);
        cudaEventCreateWithFlags(&evFork, cudaEventDisableTiming);
        cudaEventCreateWithFlags(&evJoin, cudaEventDisableTiming);
        init_done = 1;
    }

    int gblk = (NT + 127) / 128;  // 157

    // fork: side stream does prep + GEMM1a (train @ W1s -> fp32 partial)
    cudaEventRecord(evFork, 0);
    cudaStreamWaitEvent(s2, evFork, 0);
    {
        dim3 gp(512, 6);
        prep_side_kernel<<<gp, 256, 0, s2>>>(train, W1s, W1n, W2s, W2n, Wc1);
    }
    mma_gemm_dual<<<gblk, 256, SM_TOTAL, s2>>>(train16, KP1, KP1, bt1s,
                                               nullptr, HID, 0, nullptr, b1, nullptr, NT,
                                               nullptr, nullptr, h1f, nullptr, 2);
    cudaEventRecord(evJoin, s2);

    // main: edge pipeline + aggregation
    {
        dim3 gp(296, 2);
        prep_main_kernel<<<gp, 256>>>(gene);
    }
    hist_kernel<<<NE / 1024, 256>>>(edst);
    scan1_kernel<<<SCAN_BLKS, 1024>>>();
    scan2b_kernel<<<1, 32>>>();
    scatter_kernel<<<NE / 1280, 256>>>(esrc, edst);
    agg_kernel<<<(NT + 7) / 8, 256>>>();

    // join: GEMM1b needs h1f (s2) + agg16 (main)
    cudaStreamWaitEvent(0, evJoin, 0);

    // h1 = relu(h1f + agg @ W1n + b1)
    mma_gemm_dual<<<gblk, 256, SM_TOTAL>>>(agg16, HID, HID, bt1n,
                                           nullptr, HID, 0, nullptr, b1, h1, NT,
                                           nullptr, nullptr, nullptr, h1f, 0);
    // h2 = relu(h1 @ W2s + agg @ W2n + b2)
    mma_gemm_dual<<<gblk, 256, SM_TOTAL>>>(h1, HID, HID, bt2s,
                                           agg16, HID, HID, bt2n, b2, h2, NT,
                                           nullptr, nullptr, nullptr, nullptr, 0);
    // out = relu(h2 @ Wc1 + bc1) @ Wc2 + bc2   (fused classifier)
    mma_gemm_dual<<<gblk, 256, SM_TOTAL>>>(h2, HID, HID, btc1,
                                           nullptr, HID, 0, nullptr, bc1, nullptr, NT,
                                           Wc2, bc2, out, nullptr, 1);
}

// round 16
// speedup vs baseline: 1.2514x; 1.0632x over previous
#include <cuda_runtime.h>
#include <cuda_fp16.h>
#include <cstdint>

#define NG 2500
#define NT 20000
#define NE 640000
#define SRCD 128
#define DSTD 500
#define HID 128
#define OUTD 128
#define NCLS 16
#define KP1 512
#define SCAN_BLKS 20
#define SCAN_SPAN 1000

// ---------------- scratch (device globals; no allocation allowed) ----------------
__device__ int    g_cnt[NT];
__device__ int    g_rowstart[NT];
__device__ int    g_bsum[SCAN_BLKS];
__device__ int    g_boff[SCAN_BLKS];
__device__ int    g_pos[NE];
__device__ int    g_sorted[NE];
__device__ float  g_h1f[(size_t)NT * HID];   // fp32 partial: train @ W1s
__device__ __half g_train16[(size_t)NT * KP1];
__device__ __half g_gene16[NG * SRCD];
__device__ __half g_agg16[(size_t)NT * HID];
__device__ __half g_Bt1s[128 * KP1];
__device__ __half g_Bt1n[128 * 128];
__device__ __half g_Bt2s[128 * 128];
__device__ __half g_Bt2n[128 * 128];
__device__ __half g_Btc1[128 * 128];

__device__ __forceinline__ uint32_t smem_to_u32(const void* p) {
    uint32_t a;
    asm("{ .reg .u64 t; cvta.to.shared.u64 t, %1; cvt.u32.u64 %0, t; }" : "=r"(a) : "l"(p));
    return a;
}
__device__ __forceinline__ uint32_t h2u(__half2 h) { return *reinterpret_cast<uint32_t*>(&h); }

// ---------------- 1a) main-stream prep ----------------
__global__ void prep_main_kernel(const float* __restrict__ gene) {
    int stride = gridDim.x * blockDim.x;
    int t0 = blockIdx.x * blockDim.x + threadIdx.x;
    if (blockIdx.y == 0) {
        int N = NG * SRCD / 4;
        for (int i = t0; i < N; i += stride) {
            float4 v = reinterpret_cast<const float4*>(gene)[i];
            uint2 u;
            u.x = h2u(__floats2half2_rn(v.x, v.y));
            u.y = h2u(__floats2half2_rn(v.z, v.w));
            reinterpret_cast<uint2*>(g_gene16)[i] = u;
        }
    } else {
        for (int i = t0; i < NT; i += stride) g_cnt[i] = 0;
    }
}

// ---------------- 1b) side-stream prep ----------------
__global__ void prep_side_kernel(const float* __restrict__ train,
                                 const float* __restrict__ W1s, const float* __restrict__ W1n,
                                 const float* __restrict__ W2s, const float* __restrict__ W2n,
                                 const float* __restrict__ Wc1) {
    int task = blockIdx.y;
    int stride = gridDim.x * blockDim.x;
    int t0 = blockIdx.x * blockDim.x + threadIdx.x;
    if (task < 5) {
        const float* src; __half* dst; int K, Kpad;
        if      (task == 0) { src = W1s; dst = g_Bt1s; K = DSTD; Kpad = KP1; }
        else if (task == 1) { src = W1n; dst = g_Bt1n; K = HID;  Kpad = 128; }
        else if (task == 2) { src = W2s; dst = g_Bt2s; K = HID;  Kpad = 128; }
        else if (task == 3) { src = W2n; dst = g_Bt2n; K = HID;  Kpad = 128; }
        else                { src = Wc1; dst = g_Btc1; K = OUTD; Kpad = 128; }
        int N = 128 * Kpad;
        for (int i = t0; i < N; i += stride) {
            int n = i / Kpad, k = i % Kpad;
            dst[i] = (k < K) ? __float2half_rn(src[k * 128 + n]) : __half(0.f);
        }
    } else {
        int N = NT * (KP1 / 8);
        for (int i = t0; i < N; i += stride) {
            int r = i >> 6;
            int k0 = (i & 63) << 3;
            float f[8];
            #pragma unroll
            for (int j = 0; j < 8; j++) {
                int k = k0 + j;
                f[j] = (k < DSTD) ? train[(size_t)r * DSTD + k] : 0.f;
            }
            uint4 u;
            u.x = h2u(__floats2half2_rn(f[0], f[1]));
            u.y = h2u(__floats2half2_rn(f[2], f[3]));
            u.z = h2u(__floats2half2_rn(f[4], f[5]));
            u.w = h2u(__floats2half2_rn(f[6], f[7]));
            *reinterpret_cast<uint4*>(&g_train16[(size_t)r * KP1 + k0]) = u;
        }
    }
}

// ---------------- 2) histogram + within-row rank (ILP 4) ----------------
__global__ void hist_kernel(const int* __restrict__ edst) {
    int base = blockIdx.x * 1024 + threadIdx.x;
    int d0 = edst[base];
    int d1 = edst[base + 256];
    int d2 = edst[base + 512];
    int d3 = edst[base + 768];
    g_pos[base      ] = atomicAdd(&g_cnt[d0], 1);
    g_pos[base + 256] = atomicAdd(&g_cnt[d1], 1);
    g_pos[base + 512] = atomicAdd(&g_cnt[d2], 1);
    g_pos[base + 768] = atomicAdd(&g_cnt[d3], 1);
}

// ---------------- 3a) block-parallel scan ----------------
__global__ __launch_bounds__(1024) void scan1_kernel() {
    __shared__ int wsum[32];
    int b = blockIdx.x;
    int t = threadIdx.x, lane = t & 31, w = t >> 5;
    int i = b * SCAN_SPAN + t;
    int v = (t < SCAN_SPAN) ? g_cnt[i] : 0;
    int incl = v;
    #pragma unroll
    for (int d = 1; d < 32; d <<= 1) {
        int x = __shfl_up_sync(0xFFFFFFFFu, incl, d);
        if (lane >= d) incl += x;
    }
    if (lane == 31) wsum[w] = incl;
    __syncthreads();
    if (w == 0) {
        int x = wsum[lane];
        #pragma unroll
        for (int d = 1; d < 32; d <<= 1) {
            int y = __shfl_up_sync(0xFFFFFFFFu, x, d);
            if (lane >= d) x += y;
        }
        wsum[lane] = x;
    }
    __syncthreads();
    int excl = (w > 0 ? wsum[w - 1] : 0) + incl - v;
    if (t < SCAN_SPAN) g_rowstart[i] = excl;
    if (t == 0) g_bsum[b] = wsum[31];
}

__global__ void scan2b_kernel() {
    int t = threadIdx.x;
    int v = (t < SCAN_BLKS) ? g_bsum[t] : 0;
    int incl = v;
    #pragma unroll
    for (int d = 1; d < 32; d <<= 1) {
        int x = __shfl_up_sync(0xFFFFFFFFu, incl, d);
        if (t >= d) incl += x;
    }
    if (t < SCAN_BLKS) g_boff[t] = incl - v;
}

// ---------------- 4) pure scatter (ILP 5) ----------------
__global__ void scatter_kernel(const int* __restrict__ esrc, const int* __restrict__ edst) {
    int base = blockIdx.x * 1280 + threadIdx.x;
    int d[5], p[5], s[5];
    #pragma unroll
    for (int j = 0; j < 5; j++) d[j] = edst[base + j * 256];
    #pragma unroll
    for (int j = 0; j < 5; j++) p[j] = g_pos[base + j * 256];
    #pragma unroll
    for (int j = 0; j < 5; j++) s[j] = esrc[base + j * 256];
    int r[5];
    #pragma unroll
    for (int j = 0; j < 5; j++) r[j] = g_rowstart[d[j]] + g_boff[d[j] / SCAN_SPAN];
    #pragma unroll
    for (int j = 0; j < 5; j++) g_sorted[r[j] + p[j]] = s[j];
}

// ---------------- 5) mean aggregation -> fp16 agg ----------------
__global__ void agg_kernel() {
    int d = blockIdx.x * 8 + (threadIdx.x >> 5);
    if (d >= NT) return;
    int lane = threadIdx.x & 31;
    int start = g_rowstart[d] + g_boff[d / SCAN_SPAN];
    int n = g_cnt[d];
    const uint2* G = reinterpret_cast<const uint2*>(g_gene16);

    float4 a0 = {0.f, 0.f, 0.f, 0.f}, a1 = a0, a2 = a0, a3 = a0;
    int e = 0;
    for (; e + 4 <= n; e += 4) {
        int s0 = g_sorted[start + e + 0];
        int s1 = g_sorted[start + e + 1];
        int s2 = g_sorted[start + e + 2];
        int s3 = g_sorted[start + e + 3];
        uint2 u0 = G[s0 * 32 + lane];
        uint2 u1 = G[s1 * 32 + lane];
        uint2 u2 = G[s2 * 32 + lane];
        uint2 u3 = G[s3 * 32 + lane];
        float2 f;
        f = __half22float2(*reinterpret_cast<__half2*>(&u0.x)); a0.x += f.x; a0.y += f.y;
        f = __half22float2(*reinterpret_cast<__half2*>(&u0.y)); a0.z += f.x; a0.w += f.y;
        f = __half22float2(*reinterpret_cast<__half2*>(&u1.x)); a1.x += f.x; a1.y += f.y;
        f = __half22float2(*reinterpret_cast<__half2*>(&u1.y)); a1.z += f.x; a1.w += f.y;
        f = __half22float2(*reinterpret_cast<__half2*>(&u2.x)); a2.x += f.x; a2.y += f.y;
        f = __half22float2(*reinterpret_cast<__half2*>(&u2.y)); a2.z += f.x; a2.w += f.y;
        f = __half22float2(*reinterpret_cast<__half2*>(&u3.x)); a3.x += f.x; a3.y += f.y;
        f = __half22float2(*reinterpret_cast<__half2*>(&u3.y)); a3.z += f.x; a3.w += f.y;
    }
    for (; e < n; e++) {
        int s = g_sorted[start + e];
        uint2 u = G[s * 32 + lane];
        float2 f;
        f = __half22float2(*reinterpret_cast<__half2*>(&u.x)); a0.x += f.x; a0.y += f.y;
        f = __half22float2(*reinterpret_cast<__half2*>(&u.y)); a0.z += f.x; a0.w += f.y;
    }
    float4 acc;
    acc.x = a0.x + a1.x + a2.x + a3.x;
    acc.y = a0.y + a1.y + a2.y + a3.y;
    acc.z = a0.z + a1.z + a2.z + a3.z;
    acc.w = a0.w + a1.w + a2.w + a3.w;
    float inv = 1.0f / fmaxf((float)n, 1.0f);
    uint2 u;
    u.x = h2u(__floats2half2_rn(acc.x * inv, acc.y * inv));
    u.y = h2u(__floats2half2_rn(acc.z * inv, acc.w * inv));
    reinterpret_cast<uint2*>(g_agg16)[(size_t)d * 32 + lane] = u;
}

// ---------------- 6) GEMM1a kernel (train @ W1s -> fp32 partial), cp.async 2-buf ---------
#define KC    64
#define KPADH 72
#define ABUFH (128 * KPADH)
#define SM_TOTAL_G1 (4 * ABUFH * 2)

__global__ __launch_bounds__(256, 2)
void gemm1a_kernel(const __half* __restrict__ A1, const __half* __restrict__ Bt1,
                   float* __restrict__ outp) {
    extern __shared__ float smemf[];
    __half* As = reinterpret_cast<__half*>(smemf);
    __half* Bs = As + 2 * ABUFH;

    int tid = threadIdx.x;
    int wid = tid >> 5, lane = tid & 31;
    int wm = wid & 3, wn = wid >> 2;
    int g  = lane >> 2, tq = lane & 3;
    int row0 = blockIdx.x * 128;
    int nct = KP1 / KC;   // 8

    auto stage = [&](int c, int buf) {
        int k0 = c * KC;
        __half* Ad = As + buf * ABUFH;
        __half* Bd = Bs + buf * ABUFH;
        #pragma unroll
        for (int i = 0; i < 4; i++) {
            int idx = tid + i * 256;
            int r = idx >> 3, seg = idx & 7;
            int gr = row0 + r;
            int ok = gr < NT;
            const __half* src = A1 + ((size_t)(ok ? gr : 0) * KP1 + k0 + seg * 8);
            uint32_t da = smem_to_u32(Ad + r * KPADH + seg * 8);
            asm volatile("cp.async.cg.shared.global [%0], [%1], 16, %2;"
                         :: "r"(da), "l"(src), "r"(ok ? 16 : 0));
            const __half* bsrc = Bt1 + ((size_t)r * KP1 + k0 + seg * 8);
            uint32_t db = smem_to_u32(Bd + r * KPADH + seg * 8);
            asm volatile("cp.async.cg.shared.global [%0], [%1], 16, %2;"
                         :: "r"(db), "l"(bsrc), "r"(16));
        }
        asm volatile("cp.async.commit_group;" ::: "memory");
    };

    float acc[2][8][4];
    #pragma unroll
    for (int mt = 0; mt < 2; mt++)
        #pragma unroll
        for (int nt = 0; nt < 8; nt++)
            #pragma unroll
            for (int q = 0; q < 4; q++) acc[mt][nt][q] = 0.f;

    int a_row = lane & 15;
    int a_koff = (lane >> 4) << 3;
    int b_row = (lane & 7) + ((lane >> 4) << 3);
    int b_koff = ((lane >> 3) & 1) << 3;

    stage(0, 0);
    #pragma unroll 1
    for (int c = 0; c < nct; c++) {
        int buf = c & 1;
        if (c + 1 < nct) {
            stage(c + 1, buf ^ 1);
            asm volatile("cp.async.wait_group 1;" ::: "memory");
        } else {
            asm volatile("cp.async.wait_group 0;" ::: "memory");
        }
        __syncthreads();
        uint32_t aAddr[2], bAddr[4];
        uint32_t abase = smem_to_u32(As + buf * ABUFH);
        uint32_t bbase = smem_to_u32(Bs + buf * ABUFH);
        #pragma unroll
        for (int mt = 0; mt < 2; mt++)
            aAddr[mt] = abase + ((wm * 32 + mt * 16 + a_row) * KPADH + a_koff) * 2;
        #pragma unroll
        for (int q = 0; q < 4; q++)
            bAddr[q] = bbase + ((wn * 64 + q * 16 + b_row) * KPADH + b_koff) * 2;
        #pragma unroll
        for (int ks = 0; ks < KC / 16; ks++) {
            int kb2 = ks * 32;
            uint32_t afr[2][4];
            #pragma unroll
            for (int mt = 0; mt < 2; mt++)
                asm volatile("ldmatrix.sync.aligned.m8n8.x4.shared.b16 {%0,%1,%2,%3}, [%4];"
                             : "=r"(afr[mt][0]), "=r"(afr[mt][1]),
                               "=r"(afr[mt][2]), "=r"(afr[mt][3])
                             : "r"(aAddr[mt] + kb2));
            uint32_t bfr[8][2];
            #pragma unroll
            for (int q = 0; q < 4; q++)
                asm volatile("ldmatrix.sync.aligned.m8n8.x4.shared.b16 {%0,%1,%2,%3}, [%4];"
                             : "=r"(bfr[2 * q][0]), "=r"(bfr[2 * q][1]),
                               "=r"(bfr[2 * q + 1][0]), "=r"(bfr[2 * q + 1][1])
                             : "r"(bAddr[q] + kb2));
            #pragma unroll
            for (int mt = 0; mt < 2; mt++)
                #pragma unroll
                for (int nt = 0; nt < 8; nt++)
                    asm volatile(
                        "mma.sync.aligned.m16n8k16.row.col.f32.f16.f16.f32 "
                        "{%0,%1,%2,%3}, {%4,%5,%6,%7}, {%8,%9}, {%0,%1,%2,%3};"
                        : "+f"(acc[mt][nt][0]), "+f"(acc[mt][nt][1]),
                          "+f"(acc[mt][nt][2]), "+f"(acc[mt][nt][3])
                        : "r"(afr[mt][0]), "r"(afr[mt][1]), "r"(afr[mt][2]), "r"(afr[mt][3]),
                          "r"(bfr[nt][0]), "r"(bfr[nt][1]));
        }
        __syncthreads();
    }
    #pragma unroll
    for (int mt = 0; mt < 2; mt++) {
        int r1 = row0 + wm * 32 + mt * 16 + g;
        int r2 = r1 + 8;
        #pragma unroll
        for (int nt = 0; nt < 8; nt++) {
            int col = wn * 64 + nt * 8 + tq * 2;
            if (r1 < NT)
                *reinterpret_cast<float2*>(outp + (size_t)r1 * 128 + col) =
                    make_float2(acc[mt][nt][0], acc[mt][nt][1]);
            if (r2 < NT)
                *reinterpret_cast<float2*>(outp + (size_t)r2 * 128 + col) =
                    make_float2(acc[mt][nt][2], acc[mt][nt][3]);
        }
    }
}

// ---------------- 7) fused network kernel: layer1b + layer2 + layer3 + classifier --------
// 128 rows/block, occ 1. sAgg (2 chunks) resident, sAct holds h1 then h2,
// sB double-buffers the 8 weight chunks through one cp.async pipeline.
#define NFLOAT_OFF (3 * ABUFH)          // floats consumed by sAgg+sAct+sB (6*ABUFH halves)
#define SB1F   NFLOAT_OFF
#define SB2F   (NFLOAT_OFF + 128)
#define SBC1F  (NFLOAT_OFF + 256)
#define SWC2F  (NFLOAT_OFF + 384)
#define SBC2F  (NFLOAT_OFF + 384 + 2048)
#define FUSED_SMEM ((NFLOAT_OFF + 2448) * 4)
#define TSTRIDE 130

__global__ __launch_bounds__(256, 1)
void fused_net_kernel(const float* __restrict__ b1, const float* __restrict__ b2,
                      const float* __restrict__ bc1, const float* __restrict__ Wc2,
                      const float* __restrict__ bc2, const float* __restrict__ h1f,
                      float* __restrict__ out) {
    extern __shared__ float smemf[];
    __half* sAgg = reinterpret_cast<__half*>(smemf);
    __half* sAct = sAgg + 2 * ABUFH;
    __half* sB   = sAct + 2 * ABUFH;
    float* sb1  = smemf + SB1F;
    float* sb2  = smemf + SB2F;
    float* sbc1 = smemf + SBC1F;
    float* sW2  = smemf + SWC2F;
    float* sb2c = smemf + SBC2F;

    int tid = threadIdx.x;
    int wid = tid >> 5, lane = tid & 31;
    int wm = wid & 3, wn = wid >> 2;
    int g  = lane >> 2, tq = lane & 3;
    int row0 = blockIdx.x * 128;

    if (tid < 128) { sb1[tid] = b1[tid]; sb2[tid] = b2[tid]; sbc1[tid] = bc1[tid]; }
    for (int i = tid; i < 128 * NCLS; i += 256) sW2[i] = Wc2[i];
    if (tid < NCLS) sb2c[tid] = bc2[tid];

    auto stageB = [&](int j) {
        const __half* Bp = (j < 2) ? g_Bt1n : (j < 4) ? g_Bt2s : (j < 6) ? g_Bt2n : g_Btc1;
        int k0 = (j & 1) * 64;
        __half* Bd = sB + (j & 1) * ABUFH;
        #pragma unroll
        for (int i = 0; i < 4; i++) {
            int idx = tid + i * 256;
            int r = idx >> 3, seg = idx & 7;
            const __half* src = Bp + ((size_t)r * 128 + k0 + seg * 8);
            uint32_t db = smem_to_u32(Bd + r * KPADH + seg * 8);
            asm volatile("cp.async.cg.shared.global [%0], [%1], 16, %2;"
                         :: "r"(db), "l"(src), "r"(16));
        }
        asm volatile("cp.async.commit_group;" ::: "memory");
    };

    // stage agg (both chunks) + B0 as group 0
    #pragma unroll
    for (int i = 0; i < 8; i++) {
        int idx = tid + i * 256;              // 0..2047
        int chunk = idx >> 10, rem = idx & 1023;
        int r = rem >> 3, seg = rem & 7;
        int gr = row0 + r;
        int ok = gr < NT;
        const __half* src = g_agg16 + ((size_t)(ok ? gr : 0) * HID + chunk * 64 + seg * 8);
        uint32_t da = smem_to_u32(sAgg + chunk * ABUFH + r * KPADH + seg * 8);
        asm volatile("cp.async.cg.shared.global [%0], [%1], 16, %2;"
                     :: "r"(da), "l"(src), "r"(ok ? 16 : 0));
    }
    stageB(0);   // commits group 0 (agg + B0)

    float acc[2][8][4];
    #pragma unroll
    for (int mt = 0; mt < 2; mt++)
        #pragma unroll
        for (int nt = 0; nt < 8; nt++)
            #pragma unroll
            for (int q = 0; q < 4; q++) acc[mt][nt][q] = 0.f;

    int a_row = lane & 15;
    int a_koff = (lane >> 4) << 3;
    int b_row = (lane & 7) + ((lane >> 4) << 3);
    int b_koff = ((lane >> 3) & 1) << 3;

    // epilogue helper: bias (+h1f) + relu -> sAct (fp16, ldmatrix layout)
    auto epi_to_act = [&](const float* biasS, bool addPin) {
        #pragma unroll
        for (int mt = 0; mt < 2; mt++) {
            int lr1 = wm * 32 + mt * 16 + g;
            int lr2 = lr1 + 8;
            int gr1 = row0 + lr1, gr2 = row0 + lr2;
            #pragma unroll
            for (int nt = 0; nt < 8; nt++) {
                int col = wn * 64 + nt * 8 + tq * 2;
                float b0v = biasS[col], b1v = biasS[col + 1];
                float v10 = acc[mt][nt][0] + b0v, v11 = acc[mt][nt][1] + b1v;
                float v20 = acc[mt][nt][2] + b0v, v21 = acc[mt][nt][3] + b1v;
                if (addPin) {
                    if (gr1 < NT) {
                        float2 p = *reinterpret_cast<const float2*>(h1f + (size_t)gr1 * 128 + col);
                        v10 += p.x; v11 += p.y;
                    }
                    if (gr2 < NT) {
                        float2 p = *reinterpret_cast<const float2*>(h1f + (size_t)gr2 * 128 + col);
                        v20 += p.x; v21 += p.y;
                    }
                }
                v10 = fmaxf(v10, 0.f); v11 = fmaxf(v11, 0.f);
                v20 = fmaxf(v20, 0.f); v21 = fmaxf(v21, 0.f);
                int coff = nt * 8 + tq * 2;
                *reinterpret_cast<uint32_t*>(&sAct[wn * ABUFH + lr1 * KPADH + coff]) =
                    h2u(__floats2half2_rn(v10, v11));
                *reinterpret_cast<uint32_t*>(&sAct[wn * ABUFH + lr2 * KPADH + coff]) =
                    h2u(__floats2half2_rn(v20, v21));
            }
        }
        #pragma unroll
        for (int mt = 0; mt < 2; mt++)
            #pragma unroll
            for (int nt = 0; nt < 8; nt++)
                #pragma unroll
                for (int q = 0; q < 4; q++) acc[mt][nt][q] = 0.f;
    };

    // 8 chunks: j=0,1 L1 (A=sAgg); j=2,3 L2 (A=sAct/h1); j=4,5 L2 (A=sAgg); j=6,7 L3 (A=sAct/h2)
    #pragma unroll 1
    for (int j = 0; j < 8; j++) {
        if (j + 1 < 8) {
            stageB(j + 1);
            asm volatile("cp.async.wait_group 1;" ::: "memory");
        } else {
            asm volatile("cp.async.wait_group 0;" ::: "memory");
        }
        __syncthreads();

        __half* Asrc = ((j >> 1) == 0 || (j >> 1) == 2) ? sAgg : sAct;
        uint32_t abase = smem_to_u32(Asrc + (j & 1) * ABUFH);
        uint32_t bbase = smem_to_u32(sB + (j & 1) * ABUFH);
        uint32_t aAddr[2], bAddr[4];
        #pragma unroll
        for (int mt = 0; mt < 2; mt++)
            aAddr[mt] = abase + ((wm * 32 + mt * 16 + a_row) * KPADH + a_koff) * 2;
        #pragma unroll
        for (int q = 0; q < 4; q++)
            bAddr[q] = bbase + ((wn * 64 + q * 16 + b_row) * KPADH + b_koff) * 2;

        #pragma unroll
        for (int ks = 0; ks < KC / 16; ks++) {
            int kb2 = ks * 32;
            uint32_t afr[2][4];
            #pragma unroll
            for (int mt = 0; mt < 2; mt++)
                asm volatile("ldmatrix.sync.aligned.m8n8.x4.shared.b16 {%0,%1,%2,%3}, [%4];"
                             : "=r"(afr[mt][0]), "=r"(afr[mt][1]),
                               "=r"(afr[mt][2]), "=r"(afr[mt][3])
                             : "r"(aAddr[mt] + kb2));
            uint32_t bfr[8][2];
            #pragma unroll
            for (int q = 0; q < 4; q++)
                asm volatile("ldmatrix.sync.aligned.m8n8.x4.shared.b16 {%0,%1,%2,%3}, [%4];"
                             : "=r"(bfr[2 * q][0]), "=r"(bfr[2 * q][1]),
                               "=r"(bfr[2 * q + 1][0]), "=r"(bfr[2 * q + 1][1])
                             : "r"(bAddr[q] + kb2));
            #pragma unroll
            for (int mt = 0; mt < 2; mt++)
                #pragma unroll
                for (int nt = 0; nt < 8; nt++)
                    asm volatile(
                        "mma.sync.aligned.m16n8k16.row.col.f32.f16.f16.f32 "
                        "{%0,%1,%2,%3}, {%4,%5,%6,%7}, {%8,%9}, {%0,%1,%2,%3};"
                        : "+f"(acc[mt][nt][0]), "+f"(acc[mt][nt][1]),
                          "+f"(acc[mt][nt][2]), "+f"(acc[mt][nt][3])
                        : "r"(afr[mt][0]), "r"(afr[mt][1]), "r"(afr[mt][2]), "r"(afr[mt][3]),
                          "r"(bfr[nt][0]), "r"(bfr[nt][1]));
        }

        if (j == 1) epi_to_act(sb1, true);    // h1 = relu(P + agg@W1n + b1)
        if (j == 5) epi_to_act(sb2, false);   // h2 = relu(h1@W2s + agg@W2n + b2)
        __syncthreads();
    }

    // layer3 epilogue + classifier; tS overlays sAgg/sAct (all mma done, sync above)
    float* tS = smemf;
    #pragma unroll
    for (int mt = 0; mt < 2; mt++) {
        int lr1 = wm * 32 + mt * 16 + g;
        int lr2 = lr1 + 8;
        #pragma unroll
        for (int nt = 0; nt < 8; nt++) {
            int col = wn * 64 + nt * 8 + tq * 2;
            float b0v = sbc1[col], b1v = sbc1[col + 1];
            tS[lr1 * TSTRIDE + col]     = fmaxf(acc[mt][nt][0] + b0v, 0.f);
            tS[lr1 * TSTRIDE + col + 1] = fmaxf(acc[mt][nt][1] + b1v, 0.f);
            tS[lr2 * TSTRIDE + col]     = fmaxf(acc[mt][nt][2] + b0v, 0.f);
            tS[lr2 * TSTRIDE + col + 1] = fmaxf(acc[mt][nt][3] + b1v, 0.f);
        }
    }
    __syncthreads();
    int lrow = tid >> 1;
    int cg = (tid & 1) * 8;
    int grow = row0 + lrow;
    if (grow < NT) {
        float s[8];
        #pragma unroll
        for (int j = 0; j < 8; j++) s[j] = sb2c[cg + j];
        #pragma unroll 4
        for (int k = 0; k < 128; k++) {
            float tv = tS[lrow * TSTRIDE + k];
            float4 w0 = *reinterpret_cast<const float4*>(&sW2[k * NCLS + cg]);
            float4 w1 = *reinterpret_cast<const float4*>(&sW2[k * NCLS + cg + 4]);
            s[0] = fmaf(tv, w0.x, s[0]); s[1] = fmaf(tv, w0.y, s[1]);
            s[2] = fmaf(tv, w0.z, s[2]); s[3] = fmaf(tv, w0.w, s[3]);
            s[4] = fmaf(tv, w1.x, s[4]); s[5] = fmaf(tv, w1.y, s[5]);
            s[6] = fmaf(tv, w1.z, s[6]); s[7] = fmaf(tv, w1.w, s[7]);
        }
        *reinterpret_cast<float4*>(out + (size_t)grow * NCLS + cg) =
            make_float4(s[0], s[1], s[2], s[3]);
        *reinterpret_cast<float4*>(out + (size_t)grow * NCLS + cg + 4) =
            make_float4(s[4], s[5], s[6], s[7]);
    }
}

// ---------------- launcher ----------------
extern "C" void kernel_launch(void* const* d_in, const int* in_sizes, int n_in,
                              void* d_out, int out_size) {
    const float* gene  = (const float*)d_in[0];
    const float* train = (const float*)d_in[1];
    const int*   esrc  = (const int*)d_in[2];
    const int*   edst  = (const int*)d_in[3];
    const float* W1n   = (const float*)d_in[4];
    const float* W1s   = (const float*)d_in[5];
    const float* b1    = (const float*)d_in[6];
    const float* W2n   = (const float*)d_in[7];
    const float* W2s   = (const float*)d_in[8];
    const float* b2    = (const float*)d_in[9];
    const float* Wc1   = (const float*)d_in[10];
    const float* bc1   = (const float*)d_in[11];
    const float* Wc2   = (const float*)d_in[12];
    const float* bc2   = (const float*)d_in[13];
    float* out = (float*)d_out;

    __half *train16, *bt1s;
    float* h1f;
    cudaGetSymbolAddress((void**)&train16, g_train16);
    cudaGetSymbolAddress((void**)&h1f,     g_h1f);
    cudaGetSymbolAddress((void**)&bt1s,    g_Bt1s);

    static cudaStream_t s2 = nullptr;
    static cudaEvent_t evFork = nullptr, evJoin = nullptr;
    static int init_done = 0;
    if (!init_done) {
        cudaFuncSetAttribute(gemm1a_kernel, cudaFuncAttributeMaxDynamicSharedMemorySize, SM_TOTAL_G1);
        cudaFuncSetAttribute(fused_net_kernel, cudaFuncAttributeMaxDynamicSharedMemorySize, FUSED_SMEM);
        cudaStreamCreateWithFlags(&s2, cudaStreamNonBlocking);
        cudaEventCreateWithFlags(&evFork, cudaEventDisableTiming);
        cudaEventCreateWithFlags(&evJoin, cudaEventDisableTiming);
        init_done = 1;
    }

    int gblk = (NT + 127) / 128;  // 157

    // fork: side stream does prep + GEMM1a (train @ W1s -> fp32 partial)
    cudaEventRecord(evFork, 0);
    cudaStreamWaitEvent(s2, evFork, 0);
    {
        dim3 gp(512, 6);
        prep_side_kernel<<<gp, 256, 0, s2>>>(train, W1s, W1n, W2s, W2n, Wc1);
    }
    gemm1a_kernel<<<gblk, 256, SM_TOTAL_G1, s2>>>(train16, bt1s, h1f);
    cudaEventRecord(evJoin, s2);

    // main: edge pipeline + aggregation
    {
        dim3 gp(296, 2);
        prep_main_kernel<<<gp, 256>>>(gene);
    }
    hist_kernel<<<NE / 1024, 256>>>(edst);
    scan1_kernel<<<SCAN_BLKS, 1024>>>();
    scan2b_kernel<<<1, 32>>>();
    scatter_kernel<<<NE / 1280, 256>>>(esrc, edst);
    agg_kernel<<<(NT + 7) / 8, 256>>>();

    // join: fused net needs h1f (s2) + agg16 (main)
    cudaStreamWaitEvent(0, evJoin, 0);

    // h1 -> h2 -> classifier, all fused on-chip
    fused_net_kernel<<<gblk, 256, FUSED_SMEM>>>(b1, b2, bc1, Wc2, bc2, h1f, out);
}